// round 9
// baseline (speedup 1.0000x reference)
#include <cuda_runtime.h>
#include <cuda_bf16.h>
#include <cstddef>

// ---------------------------------------------------------------------------
// Fused self-attention block, fp32 SIMT.
//   x:          (8, 768, 32, 32)  == (B, C, S) with S contiguous
//   in_proj_w:  (2304, 768)
//   in_proj_b:  (2304,)
//   out_proj_w: (768, 768)
//   out_proj_b: (768,)
//   out:        (8, 768, 32, 32)
//
// Pipeline (all layouts channels-major, seq contiguous -> zero transposes):
//   1) qkv[b,m,s] = sum_k Win[m,k] * x[b,k,s] + bin[m]        (GEMM, M=2304)
//   2) per (b, head): flash attention on (64 x 1024) Q/K/V slabs
//      att[b, h*64+d, s] = softmax(Q^T K / 8) @ V^T
//   3) out[b,m,s] = sum_k Wout[m,k] * att[b,k,s] + bout[m]    (GEMM, M=768)
// ---------------------------------------------------------------------------

#define BATCH   8
#define C_DIM   768
#define C3      2304
#define SEQ     1024
#define NHEADS  12
#define DHEAD   64

// Scratch (uninitialized __device__ globals — allocation-guard safe)
__device__ float g_qkv[(size_t)BATCH * C3 * SEQ];     // (B, 2304, 1024)  ~75.5 MB
__device__ float g_att[(size_t)BATCH * C_DIM * SEQ];  // (B,  768, 1024)  ~25 MB

// ---------------------------------------------------------------------------
// GEMM: Out[b] (M x 1024) = W (M x 768) @ X[b] (768 x 1024) + bias
// Tiles: BM=128, BN=128, BK=8. 256 threads, each computes an 8x8 micro-tile.
// Per kk-step: 4 LDS.128 + 64 FFMA per thread -> FMA-pipe bound.
// ---------------------------------------------------------------------------
__global__ __launch_bounds__(256)
void gemm_bias_kernel(const float* __restrict__ W,
                      const float* __restrict__ X,
                      const float* __restrict__ bias,
                      float* __restrict__ Out,
                      int M)
{
    const int K = C_DIM;   // 768
    const int N = SEQ;     // 1024

    __shared__ float As[8][128];   // As[kk][m_local]
    __shared__ float Bs[8][128];   // Bs[kk][n_local]

    const int bz = blockIdx.z;
    const int m0 = blockIdx.y * 128;
    const int n0 = blockIdx.x * 128;

    const float* Xb = X + (size_t)bz * K * N;
    float*       Ob = Out + (size_t)bz * M * N;

    const int tid = threadIdx.x;
    const int tx  = tid & 15;    // n sub-tile (8 cols)
    const int ty  = tid >> 4;    // m sub-tile (8 rows)

    // A loader: row = tid/2 (0..127), k offset = (tid&1)*4  -> one float4 / thread
    const int arow = tid >> 1;
    const int acol = (tid & 1) * 4;
    // B loader: k row = tid/32 (0..7), n offset = (tid&31)*4 -> one float4 / thread
    const int brow = tid >> 5;
    const int bcol = (tid & 31) * 4;

    float acc[8][8];
    #pragma unroll
    for (int i = 0; i < 8; i++)
        #pragma unroll
        for (int j = 0; j < 8; j++) acc[i][j] = 0.f;

    for (int k0 = 0; k0 < K; k0 += 8) {
        // Load A tile (transpose on store: As[kk][m])
        float4 wa = *(const float4*)&W[(size_t)(m0 + arow) * K + k0 + acol];
        As[acol + 0][arow] = wa.x;
        As[acol + 1][arow] = wa.y;
        As[acol + 2][arow] = wa.z;
        As[acol + 3][arow] = wa.w;
        // Load B tile (coalesced, direct)
        *(float4*)&Bs[brow][bcol] =
            *(const float4*)&Xb[(size_t)(k0 + brow) * N + n0 + bcol];
        __syncthreads();

        #pragma unroll
        for (int kk = 0; kk < 8; kk++) {
            float a[8], b[8];
            *(float4*)&a[0] = *(const float4*)&As[kk][ty * 8];
            *(float4*)&a[4] = *(const float4*)&As[kk][ty * 8 + 4];
            *(float4*)&b[0] = *(const float4*)&Bs[kk][tx * 8];
            *(float4*)&b[4] = *(const float4*)&Bs[kk][tx * 8 + 4];
            #pragma unroll
            for (int i = 0; i < 8; i++)
                #pragma unroll
                for (int j = 0; j < 8; j++)
                    acc[i][j] = fmaf(a[i], b[j], acc[i][j]);
        }
        __syncthreads();
    }

    #pragma unroll
    for (int i = 0; i < 8; i++) {
        int m = m0 + ty * 8 + i;
        float bv = bias[m];
        #pragma unroll
        for (int j4 = 0; j4 < 8; j4 += 4) {
            float4 v;
            v.x = acc[i][j4 + 0] + bv;
            v.y = acc[i][j4 + 1] + bv;
            v.z = acc[i][j4 + 2] + bv;
            v.w = acc[i][j4 + 3] + bv;
            *(float4*)&Ob[(size_t)m * N + n0 + tx * 8 + j4] = v;
        }
    }
}

// ---------------------------------------------------------------------------
// Flash attention per (batch, head, q-tile of 64).
// Q/K/V slabs are (64 d x 1024 s), d stride = 1024, s contiguous.
// Shared (dynamic): Qs[64][65] (d,q) | KVs[64][65] (d,k; K then V) | Ps[64][65] (q,k)
// Threads 16x16; thread (ty,tx) owns q rows ty*4.. and (k or d) cols tx*4..
// ---------------------------------------------------------------------------
#define FA_SMEM_FLOATS (3 * 64 * 65)

__global__ __launch_bounds__(256)
void flash_attn_kernel(const float* __restrict__ QKV,
                       float* __restrict__ AttOut)
{
    extern __shared__ float sm[];
    float (*Qs)[65]  = (float(*)[65])(sm);
    float (*KVs)[65] = (float(*)[65])(sm + 64 * 65);
    float (*Ps)[65]  = (float(*)[65])(sm + 2 * 64 * 65);

    const int b  = blockIdx.z;
    const int h  = blockIdx.y;
    const int q0 = blockIdx.x * 64;

    const float* Qb = QKV + ((size_t)b * C3 + h * DHEAD) * SEQ;
    const float* Kb = QKV + ((size_t)b * C3 + C_DIM + h * DHEAD) * SEQ;
    const float* Vb = QKV + ((size_t)b * C3 + 2 * C_DIM + h * DHEAD) * SEQ;

    const int tid = threadIdx.x;
    const int tx  = tid & 15;
    const int ty  = tid >> 4;
    const int lq  = tid & 63;   // loader: seq index
    const int ld0 = tid >> 6;   // loader: d base (0..3)

    // Load Q tile: Qs[d][q]
    #pragma unroll
    for (int r = 0; r < 16; r++) {
        int d = ld0 + r * 4;
        Qs[d][lq] = Qb[(size_t)d * SEQ + q0 + lq];
    }

    float o[4][4];
    float mrow[4], lrow[4];
    #pragma unroll
    for (int i = 0; i < 4; i++) {
        mrow[i] = -1e30f; lrow[i] = 0.f;
        #pragma unroll
        for (int j = 0; j < 4; j++) o[i][j] = 0.f;
    }

    __syncthreads();

    const float scale = 0.125f;  // 1/sqrt(64)

    for (int kt = 0; kt < SEQ / 64; kt++) {
        const int k0 = kt * 64;

        // Load K tile into KVs[d][k]
        #pragma unroll
        for (int r = 0; r < 16; r++) {
            int d = ld0 + r * 4;
            KVs[d][lq] = Kb[(size_t)d * SEQ + k0 + lq];
        }
        __syncthreads();

        // S = Q^T K  -> s[qi][kj]
        float s[4][4];
        #pragma unroll
        for (int i = 0; i < 4; i++)
            #pragma unroll
            for (int j = 0; j < 4; j++) s[i][j] = 0.f;

        #pragma unroll 8
        for (int d = 0; d < 64; d++) {
            float a[4], c[4];
            #pragma unroll
            for (int i = 0; i < 4; i++) a[i] = Qs[d][ty * 4 + i];
            #pragma unroll
            for (int j = 0; j < 4; j++) c[j] = KVs[d][tx * 4 + j];
            #pragma unroll
            for (int i = 0; i < 4; i++)
                #pragma unroll
                for (int j = 0; j < 4; j++)
                    s[i][j] = fmaf(a[i], c[j], s[i][j]);
        }

        // Online softmax update (row reductions across the 16 tx lanes)
        #pragma unroll
        for (int i = 0; i < 4; i++) {
            float mx = fmaxf(fmaxf(s[i][0], s[i][1]), fmaxf(s[i][2], s[i][3]));
            #pragma unroll
            for (int off = 8; off >= 1; off >>= 1)
                mx = fmaxf(mx, __shfl_xor_sync(0xffffffffu, mx, off, 16));
            mx *= scale;
            float mnew = fmaxf(mrow[i], mx);
            float corr = __expf(mrow[i] - mnew);

            float rsum = 0.f;
            #pragma unroll
            for (int j = 0; j < 4; j++) {
                float p = __expf(s[i][j] * scale - mnew);
                Ps[ty * 4 + i][tx * 4 + j] = p;
                rsum += p;
            }
            #pragma unroll
            for (int off = 8; off >= 1; off >>= 1)
                rsum += __shfl_xor_sync(0xffffffffu, rsum, off, 16);

            lrow[i] = lrow[i] * corr + rsum;
            mrow[i] = mnew;
            #pragma unroll
            for (int j = 0; j < 4; j++) o[i][j] *= corr;
        }
        __syncthreads();  // Ps visible; KVs (K) no longer needed

        // Load V tile into KVs[d][k]
        #pragma unroll
        for (int r = 0; r < 16; r++) {
            int d = ld0 + r * 4;
            KVs[d][lq] = Vb[(size_t)d * SEQ + k0 + lq];
        }
        __syncthreads();

        // O += P @ V^T : o[qi][dj] += sum_k Ps[q][k] * KVs[d][k]
        #pragma unroll 8
        for (int k = 0; k < 64; k++) {
            float a[4], c[4];
            #pragma unroll
            for (int i = 0; i < 4; i++) a[i] = Ps[ty * 4 + i][k];
            #pragma unroll
            for (int j = 0; j < 4; j++) c[j] = KVs[tx * 4 + j][k];
            #pragma unroll
            for (int i = 0; i < 4; i++)
                #pragma unroll
                for (int j = 0; j < 4; j++)
                    o[i][j] = fmaf(a[i], c[j], o[i][j]);
        }
        __syncthreads();  // before next iteration overwrites KVs / Ps
    }

    // Normalize and stage transposed into Ps as Os[d][q] for coalesced store
    #pragma unroll
    for (int i = 0; i < 4; i++) {
        float inv = 1.0f / lrow[i];
        #pragma unroll
        for (int j = 0; j < 4; j++)
            Ps[tx * 4 + j][ty * 4 + i] = o[i][j] * inv;
    }
    __syncthreads();

    float* Ob = AttOut + ((size_t)b * C_DIM + h * DHEAD) * SEQ;
    #pragma unroll
    for (int r = 0; r < 16; r++) {
        int d = ld0 + r * 4;
        Ob[(size_t)d * SEQ + q0 + lq] = Ps[d][lq];
    }
}

// ---------------------------------------------------------------------------
// Launch
// ---------------------------------------------------------------------------
extern "C" void kernel_launch(void* const* d_in, const int* in_sizes, int n_in,
                              void* d_out, int out_size)
{
    const float* x     = (const float*)d_in[0];
    const float* w_in  = (const float*)d_in[1];
    const float* b_in  = (const float*)d_in[2];
    const float* w_out = (const float*)d_in[3];
    const float* b_out = (const float*)d_in[4];
    float* out = (float*)d_out;

    float* qkv = nullptr;
    float* att = nullptr;
    cudaGetSymbolAddress((void**)&qkv, g_qkv);
    cudaGetSymbolAddress((void**)&att, g_att);

    const int fa_smem = FA_SMEM_FLOATS * (int)sizeof(float);  // 49,920 B
    cudaFuncSetAttribute(flash_attn_kernel,
                         cudaFuncAttributeMaxDynamicSharedMemorySize, fa_smem);

    // 1) QKV projection: (B, 2304, 1024)
    gemm_bias_kernel<<<dim3(SEQ / 128, C3 / 128, BATCH), 256>>>(
        w_in, x, b_in, qkv, C3);

    // 2) Flash attention per (q-tile, head, batch)
    flash_attn_kernel<<<dim3(SEQ / 64, NHEADS, BATCH), 256, fa_smem>>>(
        qkv, att);

    // 3) Output projection straight into d_out: (B, 768, 1024) == (B,C,H,W)
    gemm_bias_kernel<<<dim3(SEQ / 128, C_DIM / 128, BATCH), 256>>>(
        w_out, att, b_out, out, C_DIM);
}

// round 11
// speedup vs baseline: 1.3749x; 1.3749x over previous
#include <cuda_runtime.h>
#include <cuda_bf16.h>
#include <cstdint>
#include <cstddef>

// ===========================================================================
// Self-attention block.
//   Projections: warp-level mma.sync bf16 split-precision (hi/lo), fp32 accum.
//   Flash attention: fp32 SIMT (unchanged from the passing R9 kernel).
//
//   x:          (8, 768, 32, 32) == (B, K, S), S contiguous
//   in_proj_w:  (2304, 768), in_proj_b: (2304,)
//   out_proj_w: (768, 768),  out_proj_b: (768,)
//   out:        (8, 768, 32, 32)
// ===========================================================================

#define BATCH   8
#define C_DIM   768
#define C3      2304
#define SEQ     1024
#define NHEADS  12
#define DHEAD   64

// ---------------- scratch (static __device__ globals; no allocation) -------
__device__ float g_qkv[(size_t)BATCH * C3 * SEQ];      // (B, 2304, 1024)
__device__ float g_att[(size_t)BATCH * C_DIM * SEQ];   // (B,  768, 1024)

__device__ __nv_bfloat16 g_win_hi[(size_t)C3 * C_DIM];
__device__ __nv_bfloat16 g_win_lo[(size_t)C3 * C_DIM];
__device__ __nv_bfloat16 g_wout_hi[(size_t)C_DIM * C_DIM];
__device__ __nv_bfloat16 g_wout_lo[(size_t)C_DIM * C_DIM];
// X and att transposed to (B, S, K) K-major: this is B^T row-major, exactly
// what mma.sync row.col wants for the B operand.
__device__ __nv_bfloat16 g_xt_hi[(size_t)BATCH * SEQ * C_DIM];
__device__ __nv_bfloat16 g_xt_lo[(size_t)BATCH * SEQ * C_DIM];
__device__ __nv_bfloat16 g_at_hi[(size_t)BATCH * SEQ * C_DIM];
__device__ __nv_bfloat16 g_at_lo[(size_t)BATCH * SEQ * C_DIM];

// ---------------------------------------------------------------------------
// Split conversions
// ---------------------------------------------------------------------------
__global__ void convert_split(const float* __restrict__ in,
                              __nv_bfloat16* __restrict__ hi,
                              __nv_bfloat16* __restrict__ lo, int n)
{
    int i = blockIdx.x * blockDim.x + threadIdx.x;
    if (i >= n) return;
    float x = in[i];
    __nv_bfloat16 h = __float2bfloat16(x);
    float r = x - __bfloat162float(h);
    hi[i] = h;
    lo[i] = __float2bfloat16(r);
}

// (B, K=768, S=1024) fp32 -> (B, S=1024, K=768) bf16 hi/lo
__global__ __launch_bounds__(256)
void convert_split_T(const float* __restrict__ in,
                     __nv_bfloat16* __restrict__ hi,
                     __nv_bfloat16* __restrict__ lo)
{
    __shared__ float t[32][33];
    const int b  = blockIdx.z;
    const int k0 = blockIdx.x * 32;
    const int s0 = blockIdx.y * 32;
    const int tx = threadIdx.x & 31;
    const int ty = threadIdx.x >> 5;  // 0..7

    const float* ib = in + ((size_t)b * C_DIM + k0) * SEQ + s0;
    #pragma unroll
    for (int r = 0; r < 4; r++) {
        int kr = ty + r * 8;
        t[kr][tx] = ib[(size_t)kr * SEQ + tx];
    }
    __syncthreads();
    const size_t ob = ((size_t)b * SEQ + s0) * C_DIM + k0;
    #pragma unroll
    for (int r = 0; r < 4; r++) {
        int sr = ty + r * 8;
        float x = t[tx][sr];
        __nv_bfloat16 h = __float2bfloat16(x);
        float res = x - __bfloat162float(h);
        hi[ob + (size_t)sr * C_DIM + tx] = h;
        lo[ob + (size_t)sr * C_DIM + tx] = __float2bfloat16(res);
    }
}

// ---------------------------------------------------------------------------
// mma.sync m16n8k16 bf16 -> f32
// ---------------------------------------------------------------------------
__device__ __forceinline__ void mma16816(float* c, const uint32_t* a,
                                         const uint32_t* b)
{
    asm volatile(
        "mma.sync.aligned.m16n8k16.row.col.f32.bf16.bf16.f32 "
        "{%0,%1,%2,%3}, {%4,%5,%6,%7}, {%8,%9}, {%0,%1,%2,%3};"
        : "+f"(c[0]), "+f"(c[1]), "+f"(c[2]), "+f"(c[3])
        : "r"(a[0]), "r"(a[1]), "r"(a[2]), "r"(a[3]), "r"(b[0]), "r"(b[1]));
}

// ---------------------------------------------------------------------------
// GEMM: Out[b] (M x 1024) fp32 = W (M x 768) @ X[b] (768 x 1024) + bias
//   A = W, row-major [m][k], bf16 hi/lo
//   B = Xt[b], row-major [n][k] (== B^T), bf16 hi/lo
// Block: 256 thr (8 warps, 4m x 2n). BM=128, BN=64, BK=32, warp tile 32x32.
// Split precision: D += Ahi*Bhi + Ahi*Blo + Alo*Bhi  (fp32 accumulate).
// ---------------------------------------------------------------------------
#define BK     32
#define LDA    40   // padded row length (bf16 elems) -> conflict-free frags
#define N_ITER (C_DIM / BK)   // 24

__global__ __launch_bounds__(256)
void gemm_mma_kernel(const __nv_bfloat16* __restrict__ Whi,
                     const __nv_bfloat16* __restrict__ Wlo,
                     const __nv_bfloat16* __restrict__ Bthi,
                     const __nv_bfloat16* __restrict__ Btlo,
                     const float* __restrict__ bias,
                     float* __restrict__ Out, int M)
{
    __shared__ __align__(16) __nv_bfloat16 sAhi[128][LDA];
    __shared__ __align__(16) __nv_bfloat16 sAlo[128][LDA];
    __shared__ __align__(16) __nv_bfloat16 sBhi[64][LDA];
    __shared__ __align__(16) __nv_bfloat16 sBlo[64][LDA];

    const int tid  = threadIdx.x;
    const int lane = tid & 31;
    const int wid  = tid >> 5;
    const int wm   = wid & 3;    // 0..3 (m)
    const int wn   = wid >> 2;   // 0..1 (n)

    const int b  = blockIdx.z;
    const int m0 = blockIdx.y * 128;
    const int n0 = blockIdx.x * 64;

    const int g = lane >> 2;     // 0..7
    const int t = lane & 3;      // 0..3

    const __nv_bfloat16* Ahi = Whi + (size_t)m0 * C_DIM;
    const __nv_bfloat16* Alo = Wlo + (size_t)m0 * C_DIM;
    const __nv_bfloat16* Bhi = Bthi + ((size_t)b * SEQ + n0) * C_DIM;
    const __nv_bfloat16* Blo = Btlo + ((size_t)b * SEQ + n0) * C_DIM;

    // Loader mapping. A: 128 rows x 4 uint4 (=64B) -> 512 loads, 2/thread.
    const int a_row0 = tid >> 2;        // via i = tid + r*256
    const int a_q    = tid & 3;
    // B: 64 rows x 4 uint4 -> 256 loads, 1/thread.
    const int b_row  = tid >> 2;
    const int b_q    = tid & 3;

    float acc[2][4][4];
    #pragma unroll
    for (int mf = 0; mf < 2; mf++)
        #pragma unroll
        for (int nf = 0; nf < 4; nf++)
            #pragma unroll
            for (int r = 0; r < 4; r++) acc[mf][nf][r] = 0.f;

    for (int kt = 0; kt < N_ITER; kt++) {
        const int k0 = kt * BK;

        // ---- fill smem tiles (uint4 = 8 bf16) ----
        #pragma unroll
        for (int r = 0; r < 2; r++) {
            int row = a_row0 + r * 64;
            const uint4* shi = (const uint4*)(Ahi + (size_t)row * C_DIM + k0) + a_q;
            const uint4* slo = (const uint4*)(Alo + (size_t)row * C_DIM + k0) + a_q;
            *(uint4*)&sAhi[row][a_q * 8] = *shi;
            *(uint4*)&sAlo[row][a_q * 8] = *slo;
        }
        {
            const uint4* shi = (const uint4*)(Bhi + (size_t)b_row * C_DIM + k0) + b_q;
            const uint4* slo = (const uint4*)(Blo + (size_t)b_row * C_DIM + k0) + b_q;
            *(uint4*)&sBhi[b_row][b_q * 8] = *shi;
            *(uint4*)&sBlo[b_row][b_q * 8] = *slo;
        }
        __syncthreads();

        // ---- compute: 2 k16 steps ----
        #pragma unroll
        for (int ks = 0; ks < 2; ks++) {
            const int kb = ks * 16;

            // B fragments for all 4 n-frags (hi & lo)
            uint32_t bh[4][2], bl[4][2];
            #pragma unroll
            for (int nf = 0; nf < 4; nf++) {
                int n = wn * 32 + nf * 8 + g;
                bh[nf][0] = *(const uint32_t*)&sBhi[n][kb + t * 2];
                bh[nf][1] = *(const uint32_t*)&sBhi[n][kb + t * 2 + 8];
                bl[nf][0] = *(const uint32_t*)&sBlo[n][kb + t * 2];
                bl[nf][1] = *(const uint32_t*)&sBlo[n][kb + t * 2 + 8];
            }

            #pragma unroll
            for (int mf = 0; mf < 2; mf++) {
                int r0 = wm * 32 + mf * 16 + g;
                int r1 = r0 + 8;
                uint32_t ah[4], al[4];
                ah[0] = *(const uint32_t*)&sAhi[r0][kb + t * 2];
                ah[1] = *(const uint32_t*)&sAhi[r1][kb + t * 2];
                ah[2] = *(const uint32_t*)&sAhi[r0][kb + t * 2 + 8];
                ah[3] = *(const uint32_t*)&sAhi[r1][kb + t * 2 + 8];
                al[0] = *(const uint32_t*)&sAlo[r0][kb + t * 2];
                al[1] = *(const uint32_t*)&sAlo[r1][kb + t * 2];
                al[2] = *(const uint32_t*)&sAlo[r0][kb + t * 2 + 8];
                al[3] = *(const uint32_t*)&sAlo[r1][kb + t * 2 + 8];

                #pragma unroll
                for (int nf = 0; nf < 4; nf++) {
                    mma16816(acc[mf][nf], ah, bh[nf]);  // hi*hi
                    mma16816(acc[mf][nf], ah, bl[nf]);  // hi*lo
                    mma16816(acc[mf][nf], al, bh[nf]);  // lo*hi
                }
            }
        }
        __syncthreads();
    }

    // ---- epilogue: bias + store (float2 per fragment half) ----
    float* Ob = Out + (size_t)b * M * SEQ;
    #pragma unroll
    for (int mf = 0; mf < 2; mf++) {
        int m_lo = m0 + wm * 32 + mf * 16 + g;
        int m_hi = m_lo + 8;
        float bv0 = bias[m_lo];
        float bv1 = bias[m_hi];
        #pragma unroll
        for (int nf = 0; nf < 4; nf++) {
            int n = n0 + wn * 32 + nf * 8 + t * 2;
            float2 v0 = make_float2(acc[mf][nf][0] + bv0, acc[mf][nf][1] + bv0);
            float2 v1 = make_float2(acc[mf][nf][2] + bv1, acc[mf][nf][3] + bv1);
            *(float2*)&Ob[(size_t)m_lo * SEQ + n] = v0;
            *(float2*)&Ob[(size_t)m_hi * SEQ + n] = v1;
        }
    }
}

// ---------------------------------------------------------------------------
// Flash attention per (batch, head, q-tile of 64) — unchanged (fp32 SIMT).
// ---------------------------------------------------------------------------
#define FA_SMEM_FLOATS (3 * 64 * 65)

__global__ __launch_bounds__(256)
void flash_attn_kernel(const float* __restrict__ QKV,
                       float* __restrict__ AttOut)
{
    extern __shared__ float sm[];
    float (*Qs)[65]  = (float(*)[65])(sm);
    float (*KVs)[65] = (float(*)[65])(sm + 64 * 65);
    float (*Ps)[65]  = (float(*)[65])(sm + 2 * 64 * 65);

    const int b  = blockIdx.z;
    const int h  = blockIdx.y;
    const int q0 = blockIdx.x * 64;

    const float* Qb = QKV + ((size_t)b * C3 + h * DHEAD) * SEQ;
    const float* Kb = QKV + ((size_t)b * C3 + C_DIM + h * DHEAD) * SEQ;
    const float* Vb = QKV + ((size_t)b * C3 + 2 * C_DIM + h * DHEAD) * SEQ;

    const int tid = threadIdx.x;
    const int tx  = tid & 15;
    const int ty  = tid >> 4;
    const int lq  = tid & 63;
    const int ld0 = tid >> 6;

    #pragma unroll
    for (int r = 0; r < 16; r++) {
        int d = ld0 + r * 4;
        Qs[d][lq] = Qb[(size_t)d * SEQ + q0 + lq];
    }

    float o[4][4];
    float mrow[4], lrow[4];
    #pragma unroll
    for (int i = 0; i < 4; i++) {
        mrow[i] = -1e30f; lrow[i] = 0.f;
        #pragma unroll
        for (int j = 0; j < 4; j++) o[i][j] = 0.f;
    }
    __syncthreads();

    const float scale = 0.125f;

    for (int kt = 0; kt < SEQ / 64; kt++) {
        const int k0 = kt * 64;

        #pragma unroll
        for (int r = 0; r < 16; r++) {
            int d = ld0 + r * 4;
            KVs[d][lq] = Kb[(size_t)d * SEQ + k0 + lq];
        }
        __syncthreads();

        float s[4][4];
        #pragma unroll
        for (int i = 0; i < 4; i++)
            #pragma unroll
            for (int j = 0; j < 4; j++) s[i][j] = 0.f;

        #pragma unroll 8
        for (int d = 0; d < 64; d++) {
            float a[4], cl[4];
            #pragma unroll
            for (int i = 0; i < 4; i++) a[i] = Qs[d][ty * 4 + i];
            #pragma unroll
            for (int j = 0; j < 4; j++) cl[j] = KVs[d][tx * 4 + j];
            #pragma unroll
            for (int i = 0; i < 4; i++)
                #pragma unroll
                for (int j = 0; j < 4; j++)
                    s[i][j] = fmaf(a[i], cl[j], s[i][j]);
        }

        #pragma unroll
        for (int i = 0; i < 4; i++) {
            float mx = fmaxf(fmaxf(s[i][0], s[i][1]), fmaxf(s[i][2], s[i][3]));
            #pragma unroll
            for (int off = 8; off >= 1; off >>= 1)
                mx = fmaxf(mx, __shfl_xor_sync(0xffffffffu, mx, off, 16));
            mx *= scale;
            float mnew = fmaxf(mrow[i], mx);
            float corr = __expf(mrow[i] - mnew);

            float rsum = 0.f;
            #pragma unroll
            for (int j = 0; j < 4; j++) {
                float p = __expf(s[i][j] * scale - mnew);
                Ps[ty * 4 + i][tx * 4 + j] = p;
                rsum += p;
            }
            #pragma unroll
            for (int off = 8; off >= 1; off >>= 1)
                rsum += __shfl_xor_sync(0xffffffffu, rsum, off, 16);

            lrow[i] = lrow[i] * corr + rsum;
            mrow[i] = mnew;
            #pragma unroll
            for (int j = 0; j < 4; j++) o[i][j] *= corr;
        }
        __syncthreads();

        #pragma unroll
        for (int r = 0; r < 16; r++) {
            int d = ld0 + r * 4;
            KVs[d][lq] = Vb[(size_t)d * SEQ + k0 + lq];
        }
        __syncthreads();

        #pragma unroll 8
        for (int k = 0; k < 64; k++) {
            float a[4], cl[4];
            #pragma unroll
            for (int i = 0; i < 4; i++) a[i] = Ps[ty * 4 + i][k];
            #pragma unroll
            for (int j = 0; j < 4; j++) cl[j] = KVs[tx * 4 + j][k];
            #pragma unroll
            for (int i = 0; i < 4; i++)
                #pragma unroll
                for (int j = 0; j < 4; j++)
                    o[i][j] = fmaf(a[i], cl[j], o[i][j]);
        }
        __syncthreads();
    }

    #pragma unroll
    for (int i = 0; i < 4; i++) {
        float inv = 1.0f / lrow[i];
        #pragma unroll
        for (int j = 0; j < 4; j++)
            Ps[tx * 4 + j][ty * 4 + i] = o[i][j] * inv;
    }
    __syncthreads();

    float* Ob = AttOut + ((size_t)b * C_DIM + h * DHEAD) * SEQ;
    #pragma unroll
    for (int r = 0; r < 16; r++) {
        int d = ld0 + r * 4;
        Ob[(size_t)d * SEQ + q0 + lq] = Ps[d][lq];
    }
}

// ---------------------------------------------------------------------------
// Launch
// ---------------------------------------------------------------------------
extern "C" void kernel_launch(void* const* d_in, const int* in_sizes, int n_in,
                              void* d_out, int out_size)
{
    const float* x     = (const float*)d_in[0];
    const float* w_in  = (const float*)d_in[1];
    const float* b_in  = (const float*)d_in[2];
    const float* w_out = (const float*)d_in[3];
    const float* b_out = (const float*)d_in[4];
    float* out = (float*)d_out;

    float *qkv, *att;
    __nv_bfloat16 *win_hi, *win_lo, *wout_hi, *wout_lo;
    __nv_bfloat16 *xt_hi, *xt_lo, *at_hi, *at_lo;
    cudaGetSymbolAddress((void**)&qkv, g_qkv);
    cudaGetSymbolAddress((void**)&att, g_att);
    cudaGetSymbolAddress((void**)&win_hi, g_win_hi);
    cudaGetSymbolAddress((void**)&win_lo, g_win_lo);
    cudaGetSymbolAddress((void**)&wout_hi, g_wout_hi);
    cudaGetSymbolAddress((void**)&wout_lo, g_wout_lo);
    cudaGetSymbolAddress((void**)&xt_hi, g_xt_hi);
    cudaGetSymbolAddress((void**)&xt_lo, g_xt_lo);
    cudaGetSymbolAddress((void**)&at_hi, g_at_hi);
    cudaGetSymbolAddress((void**)&at_lo, g_at_lo);

    const int fa_smem = FA_SMEM_FLOATS * (int)sizeof(float);
    cudaFuncSetAttribute(flash_attn_kernel,
                         cudaFuncAttributeMaxDynamicSharedMemorySize, fa_smem);

    // Split conversions (weights + transposed activations)
    {
        int n1 = C3 * C_DIM;
        convert_split<<<(n1 + 255) / 256, 256>>>(w_in, win_hi, win_lo, n1);
        int n2 = C_DIM * C_DIM;
        convert_split<<<(n2 + 255) / 256, 256>>>(w_out, wout_hi, wout_lo, n2);
        convert_split_T<<<dim3(C_DIM / 32, SEQ / 32, BATCH), 256>>>(x, xt_hi, xt_lo);
    }

    // 1) QKV projection on tensor cores (mma.sync): (B, 2304, 1024)
    gemm_mma_kernel<<<dim3(SEQ / 64, C3 / 128, BATCH), 256>>>(
        win_hi, win_lo, xt_hi, xt_lo, b_in, qkv, C3);

    // 2) Flash attention
    flash_attn_kernel<<<dim3(SEQ / 64, NHEADS, BATCH), 256, fa_smem>>>(qkv, att);

    // 3) Transpose+split attention output, then out-projection into d_out
    convert_split_T<<<dim3(C_DIM / 32, SEQ / 32, BATCH), 256>>>(att, at_hi, at_lo);
    gemm_mma_kernel<<<dim3(SEQ / 64, C_DIM / 128, BATCH), 256>>>(
        wout_hi, wout_lo, at_hi, at_lo, b_out, out, C_DIM);
}

// round 12
// speedup vs baseline: 1.8579x; 1.3512x over previous
#include <cuda_runtime.h>
#include <cuda_bf16.h>
#include <cstdint>
#include <cstddef>

// ===========================================================================
// Self-attention block, all matmuls on tensor cores (mma.sync, bf16 split
// precision hi/lo with fp32 accumulate).
//   x:          (8, 768, 32, 32) == (B, K, S), S contiguous
//   in_proj_w:  (2304, 768), in_proj_b: (2304,)
//   out_proj_w: (768, 768),  out_proj_b: (768,)
//   out:        (8, 768, 32, 32)
// ===========================================================================

#define BATCH   8
#define C_DIM   768
#define C3      2304
#define SEQ     1024
#define NHEADS  12
#define DHEAD   64

// ---------------- scratch (static __device__ globals; no allocation) -------
__device__ float g_qkv[(size_t)BATCH * C3 * SEQ];      // (B, 2304, 1024)
__device__ float g_att[(size_t)BATCH * C_DIM * SEQ];   // (B,  768, 1024)

__device__ __nv_bfloat16 g_win_hi[(size_t)C3 * C_DIM];
__device__ __nv_bfloat16 g_win_lo[(size_t)C3 * C_DIM];
__device__ __nv_bfloat16 g_wout_hi[(size_t)C_DIM * C_DIM];
__device__ __nv_bfloat16 g_wout_lo[(size_t)C_DIM * C_DIM];
__device__ __nv_bfloat16 g_xt_hi[(size_t)BATCH * SEQ * C_DIM];
__device__ __nv_bfloat16 g_xt_lo[(size_t)BATCH * SEQ * C_DIM];
__device__ __nv_bfloat16 g_at_hi[(size_t)BATCH * SEQ * C_DIM];
__device__ __nv_bfloat16 g_at_lo[(size_t)BATCH * SEQ * C_DIM];

// ---------------------------------------------------------------------------
// mma.sync m16n8k16 bf16 -> f32
// ---------------------------------------------------------------------------
__device__ __forceinline__ void mma16816(float* c, const uint32_t* a,
                                         const uint32_t* b)
{
    asm volatile(
        "mma.sync.aligned.m16n8k16.row.col.f32.bf16.bf16.f32 "
        "{%0,%1,%2,%3}, {%4,%5,%6,%7}, {%8,%9}, {%0,%1,%2,%3};"
        : "+f"(c[0]), "+f"(c[1]), "+f"(c[2]), "+f"(c[3])
        : "r"(a[0]), "r"(a[1]), "r"(a[2]), "r"(a[3]), "r"(b[0]), "r"(b[1]));
}

__device__ __forceinline__ void split_pack(float x0, float x1,
                                           uint32_t& hi, uint32_t& lo)
{
    __nv_bfloat16 h0 = __float2bfloat16(x0);
    __nv_bfloat16 h1 = __float2bfloat16(x1);
    __nv_bfloat16 l0 = __float2bfloat16(x0 - __bfloat162float(h0));
    __nv_bfloat16 l1 = __float2bfloat16(x1 - __bfloat162float(h1));
    hi = (uint32_t)*(uint16_t*)&h0 | ((uint32_t)*(uint16_t*)&h1 << 16);
    lo = (uint32_t)*(uint16_t*)&l0 | ((uint32_t)*(uint16_t*)&l1 << 16);
}

// ---------------------------------------------------------------------------
// Split conversions
// ---------------------------------------------------------------------------
__global__ void convert_split(const float* __restrict__ in,
                              __nv_bfloat16* __restrict__ hi,
                              __nv_bfloat16* __restrict__ lo, int n)
{
    int i = blockIdx.x * blockDim.x + threadIdx.x;
    if (i >= n) return;
    float x = in[i];
    __nv_bfloat16 h = __float2bfloat16(x);
    float r = x - __bfloat162float(h);
    hi[i] = h;
    lo[i] = __float2bfloat16(r);
}

// (B, K=768, S=1024) fp32 -> (B, S=1024, K=768) bf16 hi/lo
__global__ __launch_bounds__(256)
void convert_split_T(const float* __restrict__ in,
                     __nv_bfloat16* __restrict__ hi,
                     __nv_bfloat16* __restrict__ lo)
{
    __shared__ float t[32][33];
    const int b  = blockIdx.z;
    const int k0 = blockIdx.x * 32;
    const int s0 = blockIdx.y * 32;
    const int tx = threadIdx.x & 31;
    const int ty = threadIdx.x >> 5;  // 0..7

    const float* ib = in + ((size_t)b * C_DIM + k0) * SEQ + s0;
    #pragma unroll
    for (int r = 0; r < 4; r++) {
        int kr = ty + r * 8;
        t[kr][tx] = ib[(size_t)kr * SEQ + tx];
    }
    __syncthreads();
    const size_t ob = ((size_t)b * SEQ + s0) * C_DIM + k0;
    #pragma unroll
    for (int r = 0; r < 4; r++) {
        int sr = ty + r * 8;
        float x = t[tx][sr];
        __nv_bfloat16 h = __float2bfloat16(x);
        float res = x - __bfloat162float(h);
        hi[ob + (size_t)sr * C_DIM + tx] = h;
        lo[ob + (size_t)sr * C_DIM + tx] = __float2bfloat16(res);
    }
}

// ---------------------------------------------------------------------------
// GEMM (unchanged from R11 passing kernel):
// Out[b] (M x 1024) fp32 = W (M x 768) @ X[b] (768 x 1024) + bias
// ---------------------------------------------------------------------------
#define BK     32
#define LDA    40
#define N_ITER (C_DIM / BK)

__global__ __launch_bounds__(256)
void gemm_mma_kernel(const __nv_bfloat16* __restrict__ Whi,
                     const __nv_bfloat16* __restrict__ Wlo,
                     const __nv_bfloat16* __restrict__ Bthi,
                     const __nv_bfloat16* __restrict__ Btlo,
                     const float* __restrict__ bias,
                     float* __restrict__ Out, int M)
{
    __shared__ __align__(16) __nv_bfloat16 sAhi[128][LDA];
    __shared__ __align__(16) __nv_bfloat16 sAlo[128][LDA];
    __shared__ __align__(16) __nv_bfloat16 sBhi[64][LDA];
    __shared__ __align__(16) __nv_bfloat16 sBlo[64][LDA];

    const int tid  = threadIdx.x;
    const int lane = tid & 31;
    const int wid  = tid >> 5;
    const int wm   = wid & 3;
    const int wn   = wid >> 2;

    const int b  = blockIdx.z;
    const int m0 = blockIdx.y * 128;
    const int n0 = blockIdx.x * 64;

    const int g = lane >> 2;
    const int t = lane & 3;

    const __nv_bfloat16* Ahi = Whi + (size_t)m0 * C_DIM;
    const __nv_bfloat16* Alo = Wlo + (size_t)m0 * C_DIM;
    const __nv_bfloat16* Bhi = Bthi + ((size_t)b * SEQ + n0) * C_DIM;
    const __nv_bfloat16* Blo = Btlo + ((size_t)b * SEQ + n0) * C_DIM;

    const int a_row0 = tid >> 2;
    const int a_q    = tid & 3;
    const int b_row  = tid >> 2;
    const int b_q    = tid & 3;

    float acc[2][4][4];
    #pragma unroll
    for (int mf = 0; mf < 2; mf++)
        #pragma unroll
        for (int nf = 0; nf < 4; nf++)
            #pragma unroll
            for (int r = 0; r < 4; r++) acc[mf][nf][r] = 0.f;

    for (int kt = 0; kt < N_ITER; kt++) {
        const int k0 = kt * BK;

        #pragma unroll
        for (int r = 0; r < 2; r++) {
            int row = a_row0 + r * 64;
            const uint4* shi = (const uint4*)(Ahi + (size_t)row * C_DIM + k0) + a_q;
            const uint4* slo = (const uint4*)(Alo + (size_t)row * C_DIM + k0) + a_q;
            *(uint4*)&sAhi[row][a_q * 8] = *shi;
            *(uint4*)&sAlo[row][a_q * 8] = *slo;
        }
        {
            const uint4* shi = (const uint4*)(Bhi + (size_t)b_row * C_DIM + k0) + b_q;
            const uint4* slo = (const uint4*)(Blo + (size_t)b_row * C_DIM + k0) + b_q;
            *(uint4*)&sBhi[b_row][b_q * 8] = *shi;
            *(uint4*)&sBlo[b_row][b_q * 8] = *slo;
        }
        __syncthreads();

        #pragma unroll
        for (int ks = 0; ks < 2; ks++) {
            const int kb = ks * 16;

            uint32_t bh[4][2], bl[4][2];
            #pragma unroll
            for (int nf = 0; nf < 4; nf++) {
                int n = wn * 32 + nf * 8 + g;
                bh[nf][0] = *(const uint32_t*)&sBhi[n][kb + t * 2];
                bh[nf][1] = *(const uint32_t*)&sBhi[n][kb + t * 2 + 8];
                bl[nf][0] = *(const uint32_t*)&sBlo[n][kb + t * 2];
                bl[nf][1] = *(const uint32_t*)&sBlo[n][kb + t * 2 + 8];
            }

            #pragma unroll
            for (int mf = 0; mf < 2; mf++) {
                int r0 = wm * 32 + mf * 16 + g;
                int r1 = r0 + 8;
                uint32_t ah[4], al[4];
                ah[0] = *(const uint32_t*)&sAhi[r0][kb + t * 2];
                ah[1] = *(const uint32_t*)&sAhi[r1][kb + t * 2];
                ah[2] = *(const uint32_t*)&sAhi[r0][kb + t * 2 + 8];
                ah[3] = *(const uint32_t*)&sAhi[r1][kb + t * 2 + 8];
                al[0] = *(const uint32_t*)&sAlo[r0][kb + t * 2];
                al[1] = *(const uint32_t*)&sAlo[r1][kb + t * 2];
                al[2] = *(const uint32_t*)&sAlo[r0][kb + t * 2 + 8];
                al[3] = *(const uint32_t*)&sAlo[r1][kb + t * 2 + 8];

                #pragma unroll
                for (int nf = 0; nf < 4; nf++) {
                    mma16816(acc[mf][nf], ah, bh[nf]);
                    mma16816(acc[mf][nf], ah, bl[nf]);
                    mma16816(acc[mf][nf], al, bh[nf]);
                }
            }
        }
        __syncthreads();
    }

    float* Ob = Out + (size_t)b * M * SEQ;
    #pragma unroll
    for (int mf = 0; mf < 2; mf++) {
        int m_lo = m0 + wm * 32 + mf * 16 + g;
        int m_hi = m_lo + 8;
        float bv0 = bias[m_lo];
        float bv1 = bias[m_hi];
        #pragma unroll
        for (int nf = 0; nf < 4; nf++) {
            int n = n0 + wn * 32 + nf * 8 + t * 2;
            float2 v0 = make_float2(acc[mf][nf][0] + bv0, acc[mf][nf][1] + bv0);
            float2 v1 = make_float2(acc[mf][nf][2] + bv1, acc[mf][nf][3] + bv1);
            *(float2*)&Ob[(size_t)m_lo * SEQ + n] = v0;
            *(float2*)&Ob[(size_t)m_hi * SEQ + n] = v1;
        }
    }
}

// ---------------------------------------------------------------------------
// Flash attention on tensor cores, per (batch, head, q-tile of 64).
// 128 threads = 4 warps; warp w owns q rows [w*16, w*16+16).
//   S = (Q/8)^T K   : A = sQ[q][d] hi/lo,  B = sK[kseq][d] hi/lo  (3 terms)
//   P: register-passed (S C-frag == PV A-frag layout), split hi/lo
//   O += P V^T      : B = sV[d][kseq] hi/lo (gmem V is [d][s]: direct copy)
// Smem: 6 bf16 buffers 64x72 (55,296 B). Output staged fp32 [d][68] over
// the K buffers after the mainloop.
// ---------------------------------------------------------------------------
#define FRP 72          // bf16 row pitch
#define FA_SMEM_BYTES (6 * 64 * FRP * 2)   // 55296

__global__ __launch_bounds__(128)
void flash_attn_mma(const float* __restrict__ QKV, float* __restrict__ AttOut)
{
    extern __shared__ char smraw[];
    __nv_bfloat16* sQhi = (__nv_bfloat16*)smraw;
    __nv_bfloat16* sQlo = sQhi + 64 * FRP;
    __nv_bfloat16* sKhi = sQlo + 64 * FRP;
    __nv_bfloat16* sKlo = sKhi + 64 * FRP;
    __nv_bfloat16* sVhi = sKlo + 64 * FRP;
    __nv_bfloat16* sVlo = sVhi + 64 * FRP;
    float* sO = (float*)(smraw + 2 * 64 * FRP * 2);  // reuses K buffers (18,432 B >= 17,408)

    const int b  = blockIdx.z;
    const int h  = blockIdx.y;
    const int q0 = blockIdx.x * 64;

    const float* Qb = QKV + ((size_t)b * C3 + h * DHEAD) * SEQ;
    const float* Kb = QKV + ((size_t)b * C3 + C_DIM + h * DHEAD) * SEQ;
    const float* Vb = QKV + ((size_t)b * C3 + 2 * C_DIM + h * DHEAD) * SEQ;

    const int tid  = threadIdx.x;
    const int lane = tid & 31;
    const int wid  = tid >> 5;
    const int g    = lane >> 2;
    const int t    = lane & 3;
    const int qw   = wid * 16;          // warp's q base in tile

    // ---- load Q tile transposed, scale 1/8 folded (exact), split hi/lo ----
    #pragma unroll
    for (int r = 0; r < 32; r++) {
        int idx = tid + r * 128;
        int d = idx >> 6, q = idx & 63;
        float v = Qb[(size_t)d * SEQ + q0 + q] * 0.125f;
        __nv_bfloat16 hi = __float2bfloat16(v);
        sQhi[q * FRP + d] = hi;
        sQlo[q * FRP + d] = __float2bfloat16(v - __bfloat162float(hi));
    }

    float o[8][4];
    float mrow[2], lrow[2];
    #pragma unroll
    for (int nt = 0; nt < 8; nt++)
        #pragma unroll
        for (int r = 0; r < 4; r++) o[nt][r] = 0.f;
    mrow[0] = mrow[1] = -1e30f;
    lrow[0] = lrow[1] = 0.f;

    __syncthreads();

    for (int kt = 0; kt < SEQ / 64; kt++) {
        const int k0 = kt * 64;

        // ---- load K (transposed) and V (direct), split hi/lo ----
        #pragma unroll
        for (int r = 0; r < 32; r++) {
            int idx = tid + r * 128;
            int d = idx >> 6, c = idx & 63;
            float kv = Kb[(size_t)d * SEQ + k0 + c];
            __nv_bfloat16 khi = __float2bfloat16(kv);
            sKhi[c * FRP + d] = khi;
            sKlo[c * FRP + d] = __float2bfloat16(kv - __bfloat162float(khi));
            float vv = Vb[(size_t)d * SEQ + k0 + c];
            __nv_bfloat16 vhi = __float2bfloat16(vv);
            sVhi[d * FRP + c] = vhi;
            sVlo[d * FRP + c] = __float2bfloat16(vv - __bfloat162float(vhi));
        }
        __syncthreads();

        // ---- S = Q^T K : 8 n-tiles x 4 k-steps x 3 split terms ----
        float s[8][4];
        #pragma unroll
        for (int nt = 0; nt < 8; nt++)
            #pragma unroll
            for (int r = 0; r < 4; r++) s[nt][r] = 0.f;

        #pragma unroll
        for (int ks = 0; ks < 4; ks++) {
            const int kb = ks * 16;
            const int r0 = qw + g, r1 = qw + 8 + g;
            uint32_t ah[4], al[4];
            ah[0] = *(const uint32_t*)&sQhi[r0 * FRP + kb + t * 2];
            ah[1] = *(const uint32_t*)&sQhi[r1 * FRP + kb + t * 2];
            ah[2] = *(const uint32_t*)&sQhi[r0 * FRP + kb + 8 + t * 2];
            ah[3] = *(const uint32_t*)&sQhi[r1 * FRP + kb + 8 + t * 2];
            al[0] = *(const uint32_t*)&sQlo[r0 * FRP + kb + t * 2];
            al[1] = *(const uint32_t*)&sQlo[r1 * FRP + kb + t * 2];
            al[2] = *(const uint32_t*)&sQlo[r0 * FRP + kb + 8 + t * 2];
            al[3] = *(const uint32_t*)&sQlo[r1 * FRP + kb + 8 + t * 2];

            #pragma unroll
            for (int nt = 0; nt < 8; nt++) {
                int n = nt * 8 + g;
                uint32_t bh[2], bl[2];
                bh[0] = *(const uint32_t*)&sKhi[n * FRP + kb + t * 2];
                bh[1] = *(const uint32_t*)&sKhi[n * FRP + kb + 8 + t * 2];
                bl[0] = *(const uint32_t*)&sKlo[n * FRP + kb + t * 2];
                bl[1] = *(const uint32_t*)&sKlo[n * FRP + kb + 8 + t * 2];
                mma16816(s[nt], ah, bh);
                mma16816(s[nt], ah, bl);
                mma16816(s[nt], al, bh);
            }
        }

        // ---- online softmax (rows g and g+8; reduce across quad lanes) ----
        #pragma unroll
        for (int ri = 0; ri < 2; ri++) {
            const int c0 = ri * 2, c1 = ri * 2 + 1;
            float mx = -1e30f;
            #pragma unroll
            for (int nt = 0; nt < 8; nt++)
                mx = fmaxf(mx, fmaxf(s[nt][c0], s[nt][c1]));
            mx = fmaxf(mx, __shfl_xor_sync(0xffffffffu, mx, 1));
            mx = fmaxf(mx, __shfl_xor_sync(0xffffffffu, mx, 2));

            float mnew = fmaxf(mrow[ri], mx);
            float corr = __expf(mrow[ri] - mnew);

            float rsum = 0.f;
            #pragma unroll
            for (int nt = 0; nt < 8; nt++) {
                float p0 = __expf(s[nt][c0] - mnew);
                float p1 = __expf(s[nt][c1] - mnew);
                s[nt][c0] = p0;
                s[nt][c1] = p1;
                rsum += p0 + p1;
            }
            rsum += __shfl_xor_sync(0xffffffffu, rsum, 1);
            rsum += __shfl_xor_sync(0xffffffffu, rsum, 2);

            lrow[ri] = lrow[ri] * corr + rsum;
            mrow[ri] = mnew;
            #pragma unroll
            for (int nt = 0; nt < 8; nt++) {
                o[nt][c0] *= corr;
                o[nt][c1] *= corr;
            }
        }

        // ---- O += P V^T : P register-passed, split hi/lo ----
        #pragma unroll
        for (int ks = 0; ks < 4; ks++) {
            uint32_t ph[4], pl[4];
            split_pack(s[2 * ks][0],     s[2 * ks][1],     ph[0], pl[0]);
            split_pack(s[2 * ks][2],     s[2 * ks][3],     ph[1], pl[1]);
            split_pack(s[2 * ks + 1][0], s[2 * ks + 1][1], ph[2], pl[2]);
            split_pack(s[2 * ks + 1][2], s[2 * ks + 1][3], ph[3], pl[3]);

            const int kb = ks * 16;
            #pragma unroll
            for (int nt = 0; nt < 8; nt++) {
                int n = nt * 8 + g;   // d index
                uint32_t bh[2], bl[2];
                bh[0] = *(const uint32_t*)&sVhi[n * FRP + kb + t * 2];
                bh[1] = *(const uint32_t*)&sVhi[n * FRP + kb + 8 + t * 2];
                bl[0] = *(const uint32_t*)&sVlo[n * FRP + kb + t * 2];
                bl[1] = *(const uint32_t*)&sVlo[n * FRP + kb + 8 + t * 2];
                mma16816(o[nt], ph, bh);
                mma16816(o[nt], ph, bl);
                mma16816(o[nt], pl, bh);
            }
        }
        __syncthreads();
    }

    // ---- epilogue: normalize, stage [d][q] fp32, coalesced store ----
    float inv0 = 1.0f / lrow[0];
    float inv1 = 1.0f / lrow[1];
    #pragma unroll
    for (int nt = 0; nt < 8; nt++) {
        int d0 = nt * 8 + t * 2;
        sO[(size_t)d0 * 68 + qw + g]           = o[nt][0] * inv0;
        sO[(size_t)(d0 + 1) * 68 + qw + g]     = o[nt][1] * inv0;
        sO[(size_t)d0 * 68 + qw + 8 + g]       = o[nt][2] * inv1;
        sO[(size_t)(d0 + 1) * 68 + qw + 8 + g] = o[nt][3] * inv1;
    }
    __syncthreads();

    float* Ob = AttOut + ((size_t)b * C_DIM + h * DHEAD) * SEQ;
    #pragma unroll
    for (int r = 0; r < 32; r++) {
        int idx = tid + r * 128;
        int d = idx >> 6, q = idx & 63;
        Ob[(size_t)d * SEQ + q0 + q] = sO[(size_t)d * 68 + q];
    }
}

// ---------------------------------------------------------------------------
// Launch
// ---------------------------------------------------------------------------
extern "C" void kernel_launch(void* const* d_in, const int* in_sizes, int n_in,
                              void* d_out, int out_size)
{
    const float* x     = (const float*)d_in[0];
    const float* w_in  = (const float*)d_in[1];
    const float* b_in  = (const float*)d_in[2];
    const float* w_out = (const float*)d_in[3];
    const float* b_out = (const float*)d_in[4];
    float* out = (float*)d_out;

    float *qkv, *att;
    __nv_bfloat16 *win_hi, *win_lo, *wout_hi, *wout_lo;
    __nv_bfloat16 *xt_hi, *xt_lo, *at_hi, *at_lo;
    cudaGetSymbolAddress((void**)&qkv, g_qkv);
    cudaGetSymbolAddress((void**)&att, g_att);
    cudaGetSymbolAddress((void**)&win_hi, g_win_hi);
    cudaGetSymbolAddress((void**)&win_lo, g_win_lo);
    cudaGetSymbolAddress((void**)&wout_hi, g_wout_hi);
    cudaGetSymbolAddress((void**)&wout_lo, g_wout_lo);
    cudaGetSymbolAddress((void**)&xt_hi, g_xt_hi);
    cudaGetSymbolAddress((void**)&xt_lo, g_xt_lo);
    cudaGetSymbolAddress((void**)&at_hi, g_at_hi);
    cudaGetSymbolAddress((void**)&at_lo, g_at_lo);

    cudaFuncSetAttribute(flash_attn_mma,
                         cudaFuncAttributeMaxDynamicSharedMemorySize,
                         FA_SMEM_BYTES);

    // Split conversions (weights + transposed activations)
    {
        int n1 = C3 * C_DIM;
        convert_split<<<(n1 + 255) / 256, 256>>>(w_in, win_hi, win_lo, n1);
        int n2 = C_DIM * C_DIM;
        convert_split<<<(n2 + 255) / 256, 256>>>(w_out, wout_hi, wout_lo, n2);
        convert_split_T<<<dim3(C_DIM / 32, SEQ / 32, BATCH), 256>>>(x, xt_hi, xt_lo);
    }

    // 1) QKV projection (mma.sync): (B, 2304, 1024)
    gemm_mma_kernel<<<dim3(SEQ / 64, C3 / 128, BATCH), 256>>>(
        win_hi, win_lo, xt_hi, xt_lo, b_in, qkv, C3);

    // 2) Flash attention on tensor cores
    flash_attn_mma<<<dim3(SEQ / 64, NHEADS, BATCH), 128, FA_SMEM_BYTES>>>(
        qkv, att);

    // 3) Transpose+split attention output, then out-projection into d_out
    convert_split_T<<<dim3(C_DIM / 32, SEQ / 32, BATCH), 256>>>(att, at_hi, at_lo);
    gemm_mma_kernel<<<dim3(SEQ / 64, C_DIM / 128, BATCH), 256>>>(
        wout_hi, wout_lo, at_hi, at_lo, b_out, out, C_DIM);
}

// round 13
// speedup vs baseline: 2.1440x; 1.1540x over previous
#include <cuda_runtime.h>
#include <cuda_bf16.h>
#include <cstdint>
#include <cstddef>

// ===========================================================================
// Self-attention block, all matmuls on tensor cores (mma.sync, bf16 split
// precision hi/lo with fp32 accumulate).
//   x:          (8, 768, 32, 32) == (B, K, S), S contiguous
//   in_proj_w:  (2304, 768), in_proj_b: (2304,)
//   out_proj_w: (768, 768),  out_proj_b: (768,)
//   out:        (8, 768, 32, 32)
// GEMMs: BM=128/BN=128/BK=32, ldmatrix fragments, cp.async double buffer.
// ===========================================================================

#define BATCH   8
#define C_DIM   768
#define C3      2304
#define SEQ     1024
#define NHEADS  12
#define DHEAD   64

// ---------------- scratch (static __device__ globals; no allocation) -------
__device__ float g_qkv[(size_t)BATCH * C3 * SEQ];      // (B, 2304, 1024)
__device__ float g_att[(size_t)BATCH * C_DIM * SEQ];   // (B,  768, 1024)

__device__ __nv_bfloat16 g_win_hi[(size_t)C3 * C_DIM];
__device__ __nv_bfloat16 g_win_lo[(size_t)C3 * C_DIM];
__device__ __nv_bfloat16 g_wout_hi[(size_t)C_DIM * C_DIM];
__device__ __nv_bfloat16 g_wout_lo[(size_t)C_DIM * C_DIM];
__device__ __nv_bfloat16 g_xt_hi[(size_t)BATCH * SEQ * C_DIM];
__device__ __nv_bfloat16 g_xt_lo[(size_t)BATCH * SEQ * C_DIM];
__device__ __nv_bfloat16 g_at_hi[(size_t)BATCH * SEQ * C_DIM];
__device__ __nv_bfloat16 g_at_lo[(size_t)BATCH * SEQ * C_DIM];

// ---------------------------------------------------------------------------
// PTX helpers
// ---------------------------------------------------------------------------
__device__ __forceinline__ void mma16816(float* c, const uint32_t* a,
                                         const uint32_t* b)
{
    asm volatile(
        "mma.sync.aligned.m16n8k16.row.col.f32.bf16.bf16.f32 "
        "{%0,%1,%2,%3}, {%4,%5,%6,%7}, {%8,%9}, {%0,%1,%2,%3};"
        : "+f"(c[0]), "+f"(c[1]), "+f"(c[2]), "+f"(c[3])
        : "r"(a[0]), "r"(a[1]), "r"(a[2]), "r"(a[3]), "r"(b[0]), "r"(b[1]));
}

__device__ __forceinline__ void ldmx4(uint32_t* r, uint32_t saddr)
{
    asm volatile("ldmatrix.sync.aligned.m8n8.x4.shared.b16 {%0,%1,%2,%3}, [%4];"
                 : "=r"(r[0]), "=r"(r[1]), "=r"(r[2]), "=r"(r[3])
                 : "r"(saddr));
}

#define CP16(dst, src) \
    asm volatile("cp.async.cg.shared.global [%0], [%1], 16;" \
                 :: "r"(dst), "l"(src) : "memory")
#define CP_COMMIT() asm volatile("cp.async.commit_group;" ::: "memory")
#define CP_WAIT(n)  asm volatile("cp.async.wait_group %0;" :: "n"(n) : "memory")

__device__ __forceinline__ void split_pack(float x0, float x1,
                                           uint32_t& hi, uint32_t& lo)
{
    __nv_bfloat16 h0 = __float2bfloat16(x0);
    __nv_bfloat16 h1 = __float2bfloat16(x1);
    __nv_bfloat16 l0 = __float2bfloat16(x0 - __bfloat162float(h0));
    __nv_bfloat16 l1 = __float2bfloat16(x1 - __bfloat162float(h1));
    hi = (uint32_t)*(uint16_t*)&h0 | ((uint32_t)*(uint16_t*)&h1 << 16);
    lo = (uint32_t)*(uint16_t*)&l0 | ((uint32_t)*(uint16_t*)&l1 << 16);
}

// ---------------------------------------------------------------------------
// Split conversions
// ---------------------------------------------------------------------------
__global__ void convert_split(const float* __restrict__ in,
                              __nv_bfloat16* __restrict__ hi,
                              __nv_bfloat16* __restrict__ lo, int n)
{
    int i = blockIdx.x * blockDim.x + threadIdx.x;
    if (i >= n) return;
    float x = in[i];
    __nv_bfloat16 h = __float2bfloat16(x);
    float r = x - __bfloat162float(h);
    hi[i] = h;
    lo[i] = __float2bfloat16(r);
}

// (B, K=768, S=1024) fp32 -> (B, S=1024, K=768) bf16 hi/lo
__global__ __launch_bounds__(256)
void convert_split_T(const float* __restrict__ in,
                     __nv_bfloat16* __restrict__ hi,
                     __nv_bfloat16* __restrict__ lo)
{
    __shared__ float t[32][33];
    const int b  = blockIdx.z;
    const int k0 = blockIdx.x * 32;
    const int s0 = blockIdx.y * 32;
    const int tx = threadIdx.x & 31;
    const int ty = threadIdx.x >> 5;  // 0..7

    const float* ib = in + ((size_t)b * C_DIM + k0) * SEQ + s0;
    #pragma unroll
    for (int r = 0; r < 4; r++) {
        int kr = ty + r * 8;
        t[kr][tx] = ib[(size_t)kr * SEQ + tx];
    }
    __syncthreads();
    const size_t ob = ((size_t)b * SEQ + s0) * C_DIM + k0;
    #pragma unroll
    for (int r = 0; r < 4; r++) {
        int sr = ty + r * 8;
        float x = t[tx][sr];
        __nv_bfloat16 h = __float2bfloat16(x);
        float res = x - __bfloat162float(h);
        hi[ob + (size_t)sr * C_DIM + tx] = h;
        lo[ob + (size_t)sr * C_DIM + tx] = __float2bfloat16(res);
    }
}

// ---------------------------------------------------------------------------
// GEMM: Out[b] (M x 1024) fp32 = W (M x 768) @ X[b] (768 x 1024) + bias
//   A = W row-major [m][k] hi/lo; B = Xt[b] row-major [n][k] hi/lo.
// BM=128, BN=128, BK=32. 8 warps (4m x 2n), warp tile 32x64.
// ldmatrix.x4 fragment loads; cp.async 2-stage pipeline.
// Smem stage: A_hi | A_lo | B_hi | B_lo, each 128 rows x 40 bf16 (80 B pitch).
// ---------------------------------------------------------------------------
#define GBK   32
#define LDA   40                       // bf16 pitch (80 B): conflict-free ldmatrix
#define ABUF  (128 * LDA * 2)          // 10240 B per matrix buffer
#define STAGE_BYTES (4 * ABUF)         // 40960 B
#define GEMM_SMEM   (2 * STAGE_BYTES)  // 81920 B
#define GN_ITER (C_DIM / GBK)          // 24

__global__ __launch_bounds__(256, 2)
void gemm_mma_kernel(const __nv_bfloat16* __restrict__ Whi,
                     const __nv_bfloat16* __restrict__ Wlo,
                     const __nv_bfloat16* __restrict__ Bthi,
                     const __nv_bfloat16* __restrict__ Btlo,
                     const float* __restrict__ bias,
                     float* __restrict__ Out, int M)
{
    extern __shared__ char gsm[];
    const uint32_t sbase = (uint32_t)__cvta_generic_to_shared(gsm);

    const int tid  = threadIdx.x;
    const int lane = tid & 31;
    const int wid  = tid >> 5;
    const int wm   = wid & 3;    // m quarter
    const int wn   = wid >> 2;   // n half

    const int b  = blockIdx.z;
    const int m0 = blockIdx.y * 128;
    const int n0 = blockIdx.x * 128;

    const int g = lane >> 2;
    const int t = lane & 3;

    const __nv_bfloat16* Ahi = Whi + (size_t)m0 * C_DIM;
    const __nv_bfloat16* Alo = Wlo + (size_t)m0 * C_DIM;
    const __nv_bfloat16* Bhi = Bthi + ((size_t)b * SEQ + n0) * C_DIM;
    const __nv_bfloat16* Blo = Btlo + ((size_t)b * SEQ + n0) * C_DIM;

    // ldmatrix per-lane indices
    const int a_row = wm * 32 + ((lane >> 3) & 1) * 8 + (lane & 7);
    const int a_k   = (lane >> 4) * 8;
    const int b_row = wn * 64 + ((lane >> 4) << 3) + (lane & 7);
    const int b_k   = ((lane >> 3) & 1) * 8;

    float acc[2][8][4];
    #pragma unroll
    for (int mf = 0; mf < 2; mf++)
        #pragma unroll
        for (int nf = 0; nf < 8; nf++)
            #pragma unroll
            for (int r = 0; r < 4; r++) acc[mf][nf][r] = 0.f;

    // ---- stage loader: 128 rows x 4 chunks of 16B per matrix ----
    auto load_stage = [&](int kt, int s) {
        const int k0 = kt * GBK;
        const uint32_t sb = sbase + s * STAGE_BYTES;
        #pragma unroll
        for (int r = 0; r < 2; r++) {
            int idx = tid + r * 256;
            int row = idx >> 2;
            int q   = idx & 3;
            uint32_t doff = (uint32_t)(row * (LDA * 2) + q * 16);
            const char* ga_h = (const char*)(Ahi + (size_t)row * C_DIM + k0) + q * 16;
            const char* ga_l = (const char*)(Alo + (size_t)row * C_DIM + k0) + q * 16;
            const char* gb_h = (const char*)(Bhi + (size_t)row * C_DIM + k0) + q * 16;
            const char* gb_l = (const char*)(Blo + (size_t)row * C_DIM + k0) + q * 16;
            CP16(sb + doff,            ga_h);
            CP16(sb + ABUF + doff,     ga_l);
            CP16(sb + 2 * ABUF + doff, gb_h);
            CP16(sb + 3 * ABUF + doff, gb_l);
        }
    };

    load_stage(0, 0);
    CP_COMMIT();

    for (int kt = 0; kt < GN_ITER; kt++) {
        const int s = kt & 1;
        if (kt + 1 < GN_ITER) {
            load_stage(kt + 1, s ^ 1);
            CP_COMMIT();
            CP_WAIT(1);
        } else {
            CP_WAIT(0);
        }
        __syncthreads();

        const uint32_t sb = sbase + s * STAGE_BYTES;
        #pragma unroll
        for (int ks = 0; ks < 2; ks++) {
            const int kb = ks * 16;

            uint32_t ah[2][4], al[2][4];
            #pragma unroll
            for (int mf = 0; mf < 2; mf++) {
                uint32_t off = (uint32_t)(((a_row + mf * 16) * LDA + a_k + kb) * 2);
                ldmx4(ah[mf], sb + off);
                ldmx4(al[mf], sb + ABUF + off);
            }

            #pragma unroll
            for (int p = 0; p < 4; p++) {
                uint32_t boff = (uint32_t)(((b_row + p * 16) * LDA + b_k + kb) * 2);
                uint32_t bh[4], bl[4];
                ldmx4(bh, sb + 2 * ABUF + boff);
                ldmx4(bl, sb + 3 * ABUF + boff);
                #pragma unroll
                for (int mf = 0; mf < 2; mf++) {
                    mma16816(acc[mf][2 * p],     ah[mf], bh);
                    mma16816(acc[mf][2 * p],     ah[mf], bl);
                    mma16816(acc[mf][2 * p],     al[mf], bh);
                    mma16816(acc[mf][2 * p + 1], ah[mf], bh + 2);
                    mma16816(acc[mf][2 * p + 1], ah[mf], bl + 2);
                    mma16816(acc[mf][2 * p + 1], al[mf], bh + 2);
                }
            }
        }
        __syncthreads();
    }

    // ---- epilogue: bias + store ----
    float* Ob = Out + (size_t)b * M * SEQ;
    #pragma unroll
    for (int mf = 0; mf < 2; mf++) {
        int m_lo = m0 + wm * 32 + mf * 16 + g;
        int m_hi = m_lo + 8;
        float bv0 = bias[m_lo];
        float bv1 = bias[m_hi];
        #pragma unroll
        for (int nf = 0; nf < 8; nf++) {
            int n = n0 + wn * 64 + nf * 8 + t * 2;
            float2 v0 = make_float2(acc[mf][nf][0] + bv0, acc[mf][nf][1] + bv0);
            float2 v1 = make_float2(acc[mf][nf][2] + bv1, acc[mf][nf][3] + bv1);
            *(float2*)&Ob[(size_t)m_lo * SEQ + n] = v0;
            *(float2*)&Ob[(size_t)m_hi * SEQ + n] = v1;
        }
    }
}

// ---------------------------------------------------------------------------
// Flash attention on tensor cores (unchanged from passing R12).
// ---------------------------------------------------------------------------
#define FRP 72
#define FA_SMEM_BYTES (6 * 64 * FRP * 2)

__global__ __launch_bounds__(128)
void flash_attn_mma(const float* __restrict__ QKV, float* __restrict__ AttOut)
{
    extern __shared__ char smraw[];
    __nv_bfloat16* sQhi = (__nv_bfloat16*)smraw;
    __nv_bfloat16* sQlo = sQhi + 64 * FRP;
    __nv_bfloat16* sKhi = sQlo + 64 * FRP;
    __nv_bfloat16* sKlo = sKhi + 64 * FRP;
    __nv_bfloat16* sVhi = sKlo + 64 * FRP;
    __nv_bfloat16* sVlo = sVhi + 64 * FRP;
    float* sO = (float*)(smraw + 2 * 64 * FRP * 2);

    const int b  = blockIdx.z;
    const int h  = blockIdx.y;
    const int q0 = blockIdx.x * 64;

    const float* Qb = QKV + ((size_t)b * C3 + h * DHEAD) * SEQ;
    const float* Kb = QKV + ((size_t)b * C3 + C_DIM + h * DHEAD) * SEQ;
    const float* Vb = QKV + ((size_t)b * C3 + 2 * C_DIM + h * DHEAD) * SEQ;

    const int tid  = threadIdx.x;
    const int lane = tid & 31;
    const int wid  = tid >> 5;
    const int g    = lane >> 2;
    const int t    = lane & 3;
    const int qw   = wid * 16;

    #pragma unroll
    for (int r = 0; r < 32; r++) {
        int idx = tid + r * 128;
        int d = idx >> 6, q = idx & 63;
        float v = Qb[(size_t)d * SEQ + q0 + q] * 0.125f;
        __nv_bfloat16 hi = __float2bfloat16(v);
        sQhi[q * FRP + d] = hi;
        sQlo[q * FRP + d] = __float2bfloat16(v - __bfloat162float(hi));
    }

    float o[8][4];
    float mrow[2], lrow[2];
    #pragma unroll
    for (int nt = 0; nt < 8; nt++)
        #pragma unroll
        for (int r = 0; r < 4; r++) o[nt][r] = 0.f;
    mrow[0] = mrow[1] = -1e30f;
    lrow[0] = lrow[1] = 0.f;

    __syncthreads();

    for (int kt = 0; kt < SEQ / 64; kt++) {
        const int k0 = kt * 64;

        #pragma unroll
        for (int r = 0; r < 32; r++) {
            int idx = tid + r * 128;
            int d = idx >> 6, c = idx & 63;
            float kv = Kb[(size_t)d * SEQ + k0 + c];
            __nv_bfloat16 khi = __float2bfloat16(kv);
            sKhi[c * FRP + d] = khi;
            sKlo[c * FRP + d] = __float2bfloat16(kv - __bfloat162float(khi));
            float vv = Vb[(size_t)d * SEQ + k0 + c];
            __nv_bfloat16 vhi = __float2bfloat16(vv);
            sVhi[d * FRP + c] = vhi;
            sVlo[d * FRP + c] = __float2bfloat16(vv - __bfloat162float(vhi));
        }
        __syncthreads();

        float s[8][4];
        #pragma unroll
        for (int nt = 0; nt < 8; nt++)
            #pragma unroll
            for (int r = 0; r < 4; r++) s[nt][r] = 0.f;

        #pragma unroll
        for (int ks = 0; ks < 4; ks++) {
            const int kb = ks * 16;
            const int r0 = qw + g, r1 = qw + 8 + g;
            uint32_t ah[4], al[4];
            ah[0] = *(const uint32_t*)&sQhi[r0 * FRP + kb + t * 2];
            ah[1] = *(const uint32_t*)&sQhi[r1 * FRP + kb + t * 2];
            ah[2] = *(const uint32_t*)&sQhi[r0 * FRP + kb + 8 + t * 2];
            ah[3] = *(const uint32_t*)&sQhi[r1 * FRP + kb + 8 + t * 2];
            al[0] = *(const uint32_t*)&sQlo[r0 * FRP + kb + t * 2];
            al[1] = *(const uint32_t*)&sQlo[r1 * FRP + kb + t * 2];
            al[2] = *(const uint32_t*)&sQlo[r0 * FRP + kb + 8 + t * 2];
            al[3] = *(const uint32_t*)&sQlo[r1 * FRP + kb + 8 + t * 2];

            #pragma unroll
            for (int nt = 0; nt < 8; nt++) {
                int n = nt * 8 + g;
                uint32_t bh[2], bl[2];
                bh[0] = *(const uint32_t*)&sKhi[n * FRP + kb + t * 2];
                bh[1] = *(const uint32_t*)&sKhi[n * FRP + kb + 8 + t * 2];
                bl[0] = *(const uint32_t*)&sKlo[n * FRP + kb + t * 2];
                bl[1] = *(const uint32_t*)&sKlo[n * FRP + kb + 8 + t * 2];
                mma16816(s[nt], ah, bh);
                mma16816(s[nt], ah, bl);
                mma16816(s[nt], al, bh);
            }
        }

        #pragma unroll
        for (int ri = 0; ri < 2; ri++) {
            const int c0 = ri * 2, c1 = ri * 2 + 1;
            float mx = -1e30f;
            #pragma unroll
            for (int nt = 0; nt < 8; nt++)
                mx = fmaxf(mx, fmaxf(s[nt][c0], s[nt][c1]));
            mx = fmaxf(mx, __shfl_xor_sync(0xffffffffu, mx, 1));
            mx = fmaxf(mx, __shfl_xor_sync(0xffffffffu, mx, 2));

            float mnew = fmaxf(mrow[ri], mx);
            float corr = __expf(mrow[ri] - mnew);

            float rsum = 0.f;
            #pragma unroll
            for (int nt = 0; nt < 8; nt++) {
                float p0 = __expf(s[nt][c0] - mnew);
                float p1 = __expf(s[nt][c1] - mnew);
                s[nt][c0] = p0;
                s[nt][c1] = p1;
                rsum += p0 + p1;
            }
            rsum += __shfl_xor_sync(0xffffffffu, rsum, 1);
            rsum += __shfl_xor_sync(0xffffffffu, rsum, 2);

            lrow[ri] = lrow[ri] * corr + rsum;
            mrow[ri] = mnew;
            #pragma unroll
            for (int nt = 0; nt < 8; nt++) {
                o[nt][c0] *= corr;
                o[nt][c1] *= corr;
            }
        }

        #pragma unroll
        for (int ks = 0; ks < 4; ks++) {
            uint32_t ph[4], pl[4];
            split_pack(s[2 * ks][0],     s[2 * ks][1],     ph[0], pl[0]);
            split_pack(s[2 * ks][2],     s[2 * ks][3],     ph[1], pl[1]);
            split_pack(s[2 * ks + 1][0], s[2 * ks + 1][1], ph[2], pl[2]);
            split_pack(s[2 * ks + 1][2], s[2 * ks + 1][3], ph[3], pl[3]);

            const int kb = ks * 16;
            #pragma unroll
            for (int nt = 0; nt < 8; nt++) {
                int n = nt * 8 + g;
                uint32_t bh[2], bl[2];
                bh[0] = *(const uint32_t*)&sVhi[n * FRP + kb + t * 2];
                bh[1] = *(const uint32_t*)&sVhi[n * FRP + kb + 8 + t * 2];
                bl[0] = *(const uint32_t*)&sVlo[n * FRP + kb + t * 2];
                bl[1] = *(const uint32_t*)&sVlo[n * FRP + kb + 8 + t * 2];
                mma16816(o[nt], ph, bh);
                mma16816(o[nt], ph, bl);
                mma16816(o[nt], pl, bh);
            }
        }
        __syncthreads();
    }

    float inv0 = 1.0f / lrow[0];
    float inv1 = 1.0f / lrow[1];
    #pragma unroll
    for (int nt = 0; nt < 8; nt++) {
        int d0 = nt * 8 + t * 2;
        sO[(size_t)d0 * 68 + qw + g]           = o[nt][0] * inv0;
        sO[(size_t)(d0 + 1) * 68 + qw + g]     = o[nt][1] * inv0;
        sO[(size_t)d0 * 68 + qw + 8 + g]       = o[nt][2] * inv1;
        sO[(size_t)(d0 + 1) * 68 + qw + 8 + g] = o[nt][3] * inv1;
    }
    __syncthreads();

    float* Ob = AttOut + ((size_t)b * C_DIM + h * DHEAD) * SEQ;
    #pragma unroll
    for (int r = 0; r < 32; r++) {
        int idx = tid + r * 128;
        int d = idx >> 6, q = idx & 63;
        Ob[(size_t)d * SEQ + q0 + q] = sO[(size_t)d * 68 + q];
    }
}

// ---------------------------------------------------------------------------
// Launch
// ---------------------------------------------------------------------------
extern "C" void kernel_launch(void* const* d_in, const int* in_sizes, int n_in,
                              void* d_out, int out_size)
{
    const float* x     = (const float*)d_in[0];
    const float* w_in  = (const float*)d_in[1];
    const float* b_in  = (const float*)d_in[2];
    const float* w_out = (const float*)d_in[3];
    const float* b_out = (const float*)d_in[4];
    float* out = (float*)d_out;

    float *qkv, *att;
    __nv_bfloat16 *win_hi, *win_lo, *wout_hi, *wout_lo;
    __nv_bfloat16 *xt_hi, *xt_lo, *at_hi, *at_lo;
    cudaGetSymbolAddress((void**)&qkv, g_qkv);
    cudaGetSymbolAddress((void**)&att, g_att);
    cudaGetSymbolAddress((void**)&win_hi, g_win_hi);
    cudaGetSymbolAddress((void**)&win_lo, g_win_lo);
    cudaGetSymbolAddress((void**)&wout_hi, g_wout_hi);
    cudaGetSymbolAddress((void**)&wout_lo, g_wout_lo);
    cudaGetSymbolAddress((void**)&xt_hi, g_xt_hi);
    cudaGetSymbolAddress((void**)&xt_lo, g_xt_lo);
    cudaGetSymbolAddress((void**)&at_hi, g_at_hi);
    cudaGetSymbolAddress((void**)&at_lo, g_at_lo);

    cudaFuncSetAttribute(flash_attn_mma,
                         cudaFuncAttributeMaxDynamicSharedMemorySize,
                         FA_SMEM_BYTES);
    cudaFuncSetAttribute(gemm_mma_kernel,
                         cudaFuncAttributeMaxDynamicSharedMemorySize,
                         GEMM_SMEM);

    // Split conversions (weights + transposed activations)
    {
        int n1 = C3 * C_DIM;
        convert_split<<<(n1 + 255) / 256, 256>>>(w_in, win_hi, win_lo, n1);
        int n2 = C_DIM * C_DIM;
        convert_split<<<(n2 + 255) / 256, 256>>>(w_out, wout_hi, wout_lo, n2);
        convert_split_T<<<dim3(C_DIM / 32, SEQ / 32, BATCH), 256>>>(x, xt_hi, xt_lo);
    }

    // 1) QKV projection (mma.sync, ldmatrix, cp.async): (B, 2304, 1024)
    gemm_mma_kernel<<<dim3(SEQ / 128, C3 / 128, BATCH), 256, GEMM_SMEM>>>(
        win_hi, win_lo, xt_hi, xt_lo, b_in, qkv, C3);

    // 2) Flash attention on tensor cores
    flash_attn_mma<<<dim3(SEQ / 64, NHEADS, BATCH), 128, FA_SMEM_BYTES>>>(
        qkv, att);

    // 3) Transpose+split attention output, then out-projection into d_out
    convert_split_T<<<dim3(C_DIM / 32, SEQ / 32, BATCH), 256>>>(att, at_hi, at_lo);
    gemm_mma_kernel<<<dim3(SEQ / 128, C_DIM / 128, BATCH), 256, GEMM_SMEM>>>(
        wout_hi, wout_lo, at_hi, at_lo, b_out, out, C_DIM);
}

// round 14
// speedup vs baseline: 3.1465x; 1.4676x over previous
#include <cuda_runtime.h>
#include <cuda_bf16.h>
#include <cstdint>
#include <cstddef>

// ===========================================================================
// Self-attention block, all matmuls on tensor cores (mma.sync, bf16 split
// precision hi/lo with fp32 accumulate).
//   x:          (8, 768, 32, 32) == (B, K, S), S contiguous
//   in_proj_w:  (2304, 768), in_proj_b: (2304,)
//   out_proj_w: (768, 768),  out_proj_b: (768,)
//   out:        (8, 768, 32, 32)
// R14: QKV GEMM epilogue emits bf16 hi/lo (Q pre-scaled); attention uses
// cp.async + swizzled smem + ldmatrix, and writes split [s][k] output
// directly for the out-projection.
// ===========================================================================

#define BATCH   8
#define C_DIM   768
#define C3      2304
#define SEQ     1024
#define NHEADS  12
#define DHEAD   64

// ---------------- scratch (static __device__ globals; no allocation) -------
__device__ __nv_bfloat16 g_qkvh[(size_t)BATCH * C3 * SEQ];   // (B,2304,S) hi
__device__ __nv_bfloat16 g_qkvl[(size_t)BATCH * C3 * SEQ];   // (B,2304,S) lo

__device__ __nv_bfloat16 g_win_hi[(size_t)C3 * C_DIM];
__device__ __nv_bfloat16 g_win_lo[(size_t)C3 * C_DIM];
__device__ __nv_bfloat16 g_wout_hi[(size_t)C_DIM * C_DIM];
__device__ __nv_bfloat16 g_wout_lo[(size_t)C_DIM * C_DIM];
__device__ __nv_bfloat16 g_xt_hi[(size_t)BATCH * SEQ * C_DIM];
__device__ __nv_bfloat16 g_xt_lo[(size_t)BATCH * SEQ * C_DIM];
__device__ __nv_bfloat16 g_at_hi[(size_t)BATCH * SEQ * C_DIM];  // [s][chan]
__device__ __nv_bfloat16 g_at_lo[(size_t)BATCH * SEQ * C_DIM];

// ---------------------------------------------------------------------------
// PTX helpers
// ---------------------------------------------------------------------------
__device__ __forceinline__ void mma16816(float* c, const uint32_t* a,
                                         const uint32_t* b)
{
    asm volatile(
        "mma.sync.aligned.m16n8k16.row.col.f32.bf16.bf16.f32 "
        "{%0,%1,%2,%3}, {%4,%5,%6,%7}, {%8,%9}, {%0,%1,%2,%3};"
        : "+f"(c[0]), "+f"(c[1]), "+f"(c[2]), "+f"(c[3])
        : "r"(a[0]), "r"(a[1]), "r"(a[2]), "r"(a[3]), "r"(b[0]), "r"(b[1]));
}

__device__ __forceinline__ void ldmx4(uint32_t* r, uint32_t saddr)
{
    asm volatile("ldmatrix.sync.aligned.m8n8.x4.shared.b16 {%0,%1,%2,%3}, [%4];"
                 : "=r"(r[0]), "=r"(r[1]), "=r"(r[2]), "=r"(r[3])
                 : "r"(saddr));
}
__device__ __forceinline__ void ldmx4t(uint32_t* r, uint32_t saddr)
{
    asm volatile("ldmatrix.sync.aligned.m8n8.x4.trans.shared.b16 {%0,%1,%2,%3}, [%4];"
                 : "=r"(r[0]), "=r"(r[1]), "=r"(r[2]), "=r"(r[3])
                 : "r"(saddr));
}

#define CP16(dst, src) \
    asm volatile("cp.async.cg.shared.global [%0], [%1], 16;" \
                 :: "r"(dst), "l"(src) : "memory")
#define CP_COMMIT() asm volatile("cp.async.commit_group;" ::: "memory")
#define CP_WAIT(n)  asm volatile("cp.async.wait_group %0;" :: "n"(n) : "memory")

__device__ __forceinline__ void split_pack(float x0, float x1,
                                           uint32_t& hi, uint32_t& lo)
{
    __nv_bfloat16 h0 = __float2bfloat16(x0);
    __nv_bfloat16 h1 = __float2bfloat16(x1);
    __nv_bfloat16 l0 = __float2bfloat16(x0 - __bfloat162float(h0));
    __nv_bfloat16 l1 = __float2bfloat16(x1 - __bfloat162float(h1));
    hi = (uint32_t)*(uint16_t*)&h0 | ((uint32_t)*(uint16_t*)&h1 << 16);
    lo = (uint32_t)*(uint16_t*)&l0 | ((uint32_t)*(uint16_t*)&l1 << 16);
}

// ---------------------------------------------------------------------------
// Split conversions (weights; x transpose)
// ---------------------------------------------------------------------------
__global__ void convert_split(const float* __restrict__ in,
                              __nv_bfloat16* __restrict__ hi,
                              __nv_bfloat16* __restrict__ lo, int n)
{
    int i = blockIdx.x * blockDim.x + threadIdx.x;
    if (i >= n) return;
    float x = in[i];
    __nv_bfloat16 h = __float2bfloat16(x);
    float r = x - __bfloat162float(h);
    hi[i] = h;
    lo[i] = __float2bfloat16(r);
}

// (B, K=768, S=1024) fp32 -> (B, S=1024, K=768) bf16 hi/lo
__global__ __launch_bounds__(256)
void convert_split_T(const float* __restrict__ in,
                     __nv_bfloat16* __restrict__ hi,
                     __nv_bfloat16* __restrict__ lo)
{
    __shared__ float t[32][33];
    const int b  = blockIdx.z;
    const int k0 = blockIdx.x * 32;
    const int s0 = blockIdx.y * 32;
    const int tx = threadIdx.x & 31;
    const int ty = threadIdx.x >> 5;

    const float* ib = in + ((size_t)b * C_DIM + k0) * SEQ + s0;
    #pragma unroll
    for (int r = 0; r < 4; r++) {
        int kr = ty + r * 8;
        t[kr][tx] = ib[(size_t)kr * SEQ + tx];
    }
    __syncthreads();
    const size_t ob = ((size_t)b * SEQ + s0) * C_DIM + k0;
    #pragma unroll
    for (int r = 0; r < 4; r++) {
        int sr = ty + r * 8;
        float x = t[tx][sr];
        __nv_bfloat16 h = __float2bfloat16(x);
        float res = x - __bfloat162float(h);
        hi[ob + (size_t)sr * C_DIM + tx] = h;
        lo[ob + (size_t)sr * C_DIM + tx] = __float2bfloat16(res);
    }
}

// ---------------------------------------------------------------------------
// GEMM: (M x 1024) = W (M x 768) @ X[b] (768 x 1024) + bias
// BM=128, BN=128, BK=32, ldmatrix + cp.async double buffer (as R13).
// Epilogue modes:
//   OutH != null: write bf16 hi/lo split, rows < scale_cut scaled by 0.125.
//   else:         write fp32 to Out.
// ---------------------------------------------------------------------------
#define GBK   32
#define LDA   40
#define ABUF  (128 * LDA * 2)
#define STAGE_BYTES (4 * ABUF)
#define GEMM_SMEM   (2 * STAGE_BYTES)
#define GN_ITER (C_DIM / GBK)

__global__ __launch_bounds__(256, 2)
void gemm_mma_kernel(const __nv_bfloat16* __restrict__ Whi,
                     const __nv_bfloat16* __restrict__ Wlo,
                     const __nv_bfloat16* __restrict__ Bthi,
                     const __nv_bfloat16* __restrict__ Btlo,
                     const float* __restrict__ bias,
                     float* __restrict__ Out,
                     __nv_bfloat16* __restrict__ OutH,
                     __nv_bfloat16* __restrict__ OutL,
                     int M, int scale_cut)
{
    extern __shared__ char gsm[];
    const uint32_t sbase = (uint32_t)__cvta_generic_to_shared(gsm);

    const int tid  = threadIdx.x;
    const int lane = tid & 31;
    const int wid  = tid >> 5;
    const int wm   = wid & 3;
    const int wn   = wid >> 2;

    const int b  = blockIdx.z;
    const int m0 = blockIdx.y * 128;
    const int n0 = blockIdx.x * 128;

    const int g = lane >> 2;
    const int t = lane & 3;

    const __nv_bfloat16* Ahi = Whi + (size_t)m0 * C_DIM;
    const __nv_bfloat16* Alo = Wlo + (size_t)m0 * C_DIM;
    const __nv_bfloat16* Bhi = Bthi + ((size_t)b * SEQ + n0) * C_DIM;
    const __nv_bfloat16* Blo = Btlo + ((size_t)b * SEQ + n0) * C_DIM;

    const int a_row = wm * 32 + ((lane >> 3) & 1) * 8 + (lane & 7);
    const int a_k   = (lane >> 4) * 8;
    const int b_row = wn * 64 + ((lane >> 4) << 3) + (lane & 7);
    const int b_k   = ((lane >> 3) & 1) * 8;

    float acc[2][8][4];
    #pragma unroll
    for (int mf = 0; mf < 2; mf++)
        #pragma unroll
        for (int nf = 0; nf < 8; nf++)
            #pragma unroll
            for (int r = 0; r < 4; r++) acc[mf][nf][r] = 0.f;

    auto load_stage = [&](int kt, int s) {
        const int k0 = kt * GBK;
        const uint32_t sb = sbase + s * STAGE_BYTES;
        #pragma unroll
        for (int r = 0; r < 2; r++) {
            int idx = tid + r * 256;
            int row = idx >> 2;
            int q   = idx & 3;
            uint32_t doff = (uint32_t)(row * (LDA * 2) + q * 16);
            const char* ga_h = (const char*)(Ahi + (size_t)row * C_DIM + k0) + q * 16;
            const char* ga_l = (const char*)(Alo + (size_t)row * C_DIM + k0) + q * 16;
            const char* gb_h = (const char*)(Bhi + (size_t)row * C_DIM + k0) + q * 16;
            const char* gb_l = (const char*)(Blo + (size_t)row * C_DIM + k0) + q * 16;
            CP16(sb + doff,            ga_h);
            CP16(sb + ABUF + doff,     ga_l);
            CP16(sb + 2 * ABUF + doff, gb_h);
            CP16(sb + 3 * ABUF + doff, gb_l);
        }
    };

    load_stage(0, 0);
    CP_COMMIT();

    for (int kt = 0; kt < GN_ITER; kt++) {
        const int s = kt & 1;
        if (kt + 1 < GN_ITER) {
            load_stage(kt + 1, s ^ 1);
            CP_COMMIT();
            CP_WAIT(1);
        } else {
            CP_WAIT(0);
        }
        __syncthreads();

        const uint32_t sb = sbase + s * STAGE_BYTES;
        #pragma unroll
        for (int ks = 0; ks < 2; ks++) {
            const int kb = ks * 16;

            uint32_t ah[2][4], al[2][4];
            #pragma unroll
            for (int mf = 0; mf < 2; mf++) {
                uint32_t off = (uint32_t)(((a_row + mf * 16) * LDA + a_k + kb) * 2);
                ldmx4(ah[mf], sb + off);
                ldmx4(al[mf], sb + ABUF + off);
            }

            #pragma unroll
            for (int p = 0; p < 4; p++) {
                uint32_t boff = (uint32_t)(((b_row + p * 16) * LDA + b_k + kb) * 2);
                uint32_t bh[4], bl[4];
                ldmx4(bh, sb + 2 * ABUF + boff);
                ldmx4(bl, sb + 3 * ABUF + boff);
                #pragma unroll
                for (int mf = 0; mf < 2; mf++) {
                    mma16816(acc[mf][2 * p],     ah[mf], bh);
                    mma16816(acc[mf][2 * p],     ah[mf], bl);
                    mma16816(acc[mf][2 * p],     al[mf], bh);
                    mma16816(acc[mf][2 * p + 1], ah[mf], bh + 2);
                    mma16816(acc[mf][2 * p + 1], ah[mf], bl + 2);
                    mma16816(acc[mf][2 * p + 1], al[mf], bh + 2);
                }
            }
        }
        __syncthreads();
    }

    // ---- epilogue ----
    if (OutH) {
        __nv_bfloat16* OH = OutH + (size_t)b * M * SEQ;
        __nv_bfloat16* OL = OutL + (size_t)b * M * SEQ;
        #pragma unroll
        for (int mf = 0; mf < 2; mf++) {
            int m_lo = m0 + wm * 32 + mf * 16 + g;
            int m_hi = m_lo + 8;
            float rs0 = (m_lo < scale_cut) ? 0.125f : 1.0f;
            float rs1 = (m_hi < scale_cut) ? 0.125f : 1.0f;
            float bv0 = bias[m_lo];
            float bv1 = bias[m_hi];
            #pragma unroll
            for (int nf = 0; nf < 8; nf++) {
                int n = n0 + wn * 64 + nf * 8 + t * 2;
                uint32_t h0, l0, h1, l1;
                split_pack((acc[mf][nf][0] + bv0) * rs0,
                           (acc[mf][nf][1] + bv0) * rs0, h0, l0);
                split_pack((acc[mf][nf][2] + bv1) * rs1,
                           (acc[mf][nf][3] + bv1) * rs1, h1, l1);
                *(uint32_t*)&OH[(size_t)m_lo * SEQ + n] = h0;
                *(uint32_t*)&OL[(size_t)m_lo * SEQ + n] = l0;
                *(uint32_t*)&OH[(size_t)m_hi * SEQ + n] = h1;
                *(uint32_t*)&OL[(size_t)m_hi * SEQ + n] = l1;
            }
        }
    } else {
        float* Ob = Out + (size_t)b * M * SEQ;
        #pragma unroll
        for (int mf = 0; mf < 2; mf++) {
            int m_lo = m0 + wm * 32 + mf * 16 + g;
            int m_hi = m_lo + 8;
            float bv0 = bias[m_lo];
            float bv1 = bias[m_hi];
            #pragma unroll
            for (int nf = 0; nf < 8; nf++) {
                int n = n0 + wn * 64 + nf * 8 + t * 2;
                float2 v0 = make_float2(acc[mf][nf][0] + bv0, acc[mf][nf][1] + bv0);
                float2 v1 = make_float2(acc[mf][nf][2] + bv1, acc[mf][nf][3] + bv1);
                *(float2*)&Ob[(size_t)m_lo * SEQ + n] = v0;
                *(float2*)&Ob[(size_t)m_hi * SEQ + n] = v1;
            }
        }
    }
}

// ---------------------------------------------------------------------------
// Flash attention on tensor cores, per (batch, head, q-tile of 64).
// Inputs: qkvh/qkvl bf16 (B,2304,S); Q rows pre-scaled by 1/8.
// Smem: 6 swizzled [r][c] 64x64 bf16 buffers (Qh,Ql,Kh,Kl,Vh,Vl), 8 KB each.
//   byte(r,c) = r*128 + (((c>>3) ^ (r&7)) << 4) + (c&7)*2
// Fragments via ldmatrix: Q,K .trans (stored [d][seq]); V direct ([d][seq]
// is exactly the [n][k] B-operand layout).
// Output: at_hi/at_lo bf16 [s][chan] (B,S,768) — out-proj's B operand.
// ---------------------------------------------------------------------------
#define FA_SMEM_BYTES (6 * 8192)

__global__ __launch_bounds__(128)
void flash_attn_mma(const __nv_bfloat16* __restrict__ qkvh,
                    const __nv_bfloat16* __restrict__ qkvl,
                    __nv_bfloat16* __restrict__ at_hi,
                    __nv_bfloat16* __restrict__ at_lo)
{
    extern __shared__ char smraw[];
    const uint32_t sb = (uint32_t)__cvta_generic_to_shared(smraw);
    const uint32_t SQH = sb, SQL = sb + 8192, SKH = sb + 16384,
                   SKL = sb + 24576, SVH = sb + 32768, SVL = sb + 40960;

    const int b  = blockIdx.z;
    const int h  = blockIdx.y;
    const int q0 = blockIdx.x * 64;

    const size_t hoff = ((size_t)b * C3 + h * DHEAD) * SEQ;
    const __nv_bfloat16* Qh = qkvh + hoff;
    const __nv_bfloat16* Ql = qkvl + hoff;
    const __nv_bfloat16* Kh = qkvh + hoff + (size_t)C_DIM * SEQ;
    const __nv_bfloat16* Kl = qkvl + hoff + (size_t)C_DIM * SEQ;
    const __nv_bfloat16* Vh = qkvh + hoff + (size_t)(2 * C_DIM) * SEQ;
    const __nv_bfloat16* Vl = qkvl + hoff + (size_t)(2 * C_DIM) * SEQ;

    const int tid  = threadIdx.x;
    const int lane = tid & 31;
    const int wid  = tid >> 5;
    const int g    = lane >> 2;
    const int t    = lane & 3;
    const int qw   = wid * 16;          // warp's q base
    const int m4   = lane >> 3;         // ldmatrix matrix id
    const int j    = lane & 7;          // ldmatrix row-in-matrix

    // stage one 64x64 bf16 tile (rows = channels, cols = seq) into smem
    auto stage_tile = [&](const __nv_bfloat16* src, uint32_t dst, int s0) {
        #pragma unroll
        for (int r = 0; r < 4; r++) {
            int i   = tid + r * 128;
            int row = i >> 3;
            int q   = i & 7;
            uint32_t d = dst + (uint32_t)(row * 128 + ((q ^ (row & 7)) << 4));
            CP16(d, (const char*)(src + (size_t)row * SEQ + s0 + q * 8));
        }
    };

    stage_tile(Qh, SQH, q0);
    stage_tile(Ql, SQL, q0);
    stage_tile(Kh, SKH, 0);
    stage_tile(Kl, SKL, 0);
    stage_tile(Vh, SVH, 0);
    stage_tile(Vl, SVL, 0);
    CP_COMMIT();

    float o[8][4];
    float mrow[2], lrow[2];
    #pragma unroll
    for (int nt = 0; nt < 8; nt++)
        #pragma unroll
        for (int r = 0; r < 4; r++) o[nt][r] = 0.f;
    mrow[0] = mrow[1] = -1e30f;
    lrow[0] = lrow[1] = 0.f;

    for (int kt = 0; kt < SEQ / 64; kt++) {
        CP_WAIT(0);
        __syncthreads();

        // ---- S = Q^T K ----
        float s[8][4];
        #pragma unroll
        for (int nt = 0; nt < 8; nt++)
            #pragma unroll
            for (int r = 0; r < 4; r++) s[nt][r] = 0.f;

        #pragma unroll
        for (int ks = 0; ks < 4; ks++) {
            const int kb = ks * 16;

            // Q A-frag [q16][d16]: trans of stored [d][q]
            int ad = kb + (m4 >> 1) * 8 + j;
            int aq = qw + (m4 & 1) * 8;
            uint32_t aoff = (uint32_t)(ad * 128 + ((((aq >> 3) & 7) ^ (ad & 7)) << 4));
            uint32_t ah[4], al[4];
            ldmx4t(ah, SQH + aoff);
            ldmx4t(al, SQL + aoff);

            #pragma unroll
            for (int p = 0; p < 4; p++) {
                // K B-frags for n-tiles 2p, 2p+1: trans of stored [d][c]
                int bd = kb + (m4 & 1) * 8 + j;
                int bc = p * 16 + (m4 >> 1) * 8;
                uint32_t boff = (uint32_t)(bd * 128 + ((((bc >> 3) & 7) ^ (bd & 7)) << 4));
                uint32_t kh[4], kl[4];
                ldmx4t(kh, SKH + boff);
                ldmx4t(kl, SKL + boff);
                mma16816(s[2 * p],     ah, kh);
                mma16816(s[2 * p],     ah, kl);
                mma16816(s[2 * p],     al, kh);
                mma16816(s[2 * p + 1], ah, kh + 2);
                mma16816(s[2 * p + 1], ah, kl + 2);
                mma16816(s[2 * p + 1], al, kh + 2);
            }
        }

        // ---- online softmax (rows g, g+8; reduce across quad lanes) ----
        #pragma unroll
        for (int ri = 0; ri < 2; ri++) {
            const int c0 = ri * 2, c1 = ri * 2 + 1;
            float mx = -1e30f;
            #pragma unroll
            for (int nt = 0; nt < 8; nt++)
                mx = fmaxf(mx, fmaxf(s[nt][c0], s[nt][c1]));
            mx = fmaxf(mx, __shfl_xor_sync(0xffffffffu, mx, 1));
            mx = fmaxf(mx, __shfl_xor_sync(0xffffffffu, mx, 2));

            float mnew = fmaxf(mrow[ri], mx);
            float corr = __expf(mrow[ri] - mnew);

            float rsum = 0.f;
            #pragma unroll
            for (int nt = 0; nt < 8; nt++) {
                float p0 = __expf(s[nt][c0] - mnew);
                float p1 = __expf(s[nt][c1] - mnew);
                s[nt][c0] = p0;
                s[nt][c1] = p1;
                rsum += p0 + p1;
            }
            rsum += __shfl_xor_sync(0xffffffffu, rsum, 1);
            rsum += __shfl_xor_sync(0xffffffffu, rsum, 2);

            lrow[ri] = lrow[ri] * corr + rsum;
            mrow[ri] = mnew;
            #pragma unroll
            for (int nt = 0; nt < 8; nt++) {
                o[nt][c0] *= corr;
                o[nt][c1] *= corr;
            }
        }

        // ---- O += P V^T : P register-passed; V frags via direct ldmatrix ----
        #pragma unroll
        for (int ks = 0; ks < 4; ks++) {
            uint32_t ph[4], pl[4];
            split_pack(s[2 * ks][0],     s[2 * ks][1],     ph[0], pl[0]);
            split_pack(s[2 * ks][2],     s[2 * ks][3],     ph[1], pl[1]);
            split_pack(s[2 * ks + 1][0], s[2 * ks + 1][1], ph[2], pl[2]);
            split_pack(s[2 * ks + 1][2], s[2 * ks + 1][3], ph[3], pl[3]);

            const int kb = ks * 16;
            #pragma unroll
            for (int p = 0; p < 4; p++) {
                // V B-frags for d-tiles 2p, 2p+1: stored [d][c] is [n][k]
                int vd = p * 16 + (m4 >> 1) * 8 + j;
                int vch = (kb >> 3) + (m4 & 1);
                uint32_t voff = (uint32_t)(vd * 128 + ((vch ^ (vd & 7)) << 4));
                uint32_t vh[4], vl[4];
                ldmx4(vh, SVH + voff);
                ldmx4(vl, SVL + voff);
                mma16816(o[2 * p],     ph, vh);
                mma16816(o[2 * p],     ph, vl);
                mma16816(o[2 * p],     pl, vh);
                mma16816(o[2 * p + 1], ph, vh + 2);
                mma16816(o[2 * p + 1], ph, vl + 2);
                mma16816(o[2 * p + 1], pl, vh + 2);
            }
        }
        __syncthreads();

        if (kt + 1 < SEQ / 64) {
            const int k0 = (kt + 1) * 64;
            stage_tile(Kh, SKH, k0);
            stage_tile(Kl, SKL, k0);
            stage_tile(Vh, SVH, k0);
            stage_tile(Vl, SVL, k0);
            CP_COMMIT();
        }
    }

    // ---- epilogue: normalize, split, write at[s][chan] directly ----
    const float inv0 = 1.0f / lrow[0];
    const float inv1 = 1.0f / lrow[1];
    const size_t rbase = ((size_t)b * SEQ + q0);
    const int cbase = h * DHEAD + t * 2;
    #pragma unroll
    for (int nt = 0; nt < 8; nt++) {
        int col = cbase + nt * 8;
        size_t i0 = (rbase + qw + g) * C_DIM + col;
        size_t i1 = (rbase + qw + 8 + g) * C_DIM + col;
        uint32_t h0, l0, h1, l1;
        split_pack(o[nt][0] * inv0, o[nt][1] * inv0, h0, l0);
        split_pack(o[nt][2] * inv1, o[nt][3] * inv1, h1, l1);
        *(uint32_t*)&at_hi[i0] = h0;
        *(uint32_t*)&at_lo[i0] = l0;
        *(uint32_t*)&at_hi[i1] = h1;
        *(uint32_t*)&at_lo[i1] = l1;
    }
}

// ---------------------------------------------------------------------------
// Launch
// ---------------------------------------------------------------------------
extern "C" void kernel_launch(void* const* d_in, const int* in_sizes, int n_in,
                              void* d_out, int out_size)
{
    const float* x     = (const float*)d_in[0];
    const float* w_in  = (const float*)d_in[1];
    const float* b_in  = (const float*)d_in[2];
    const float* w_out = (const float*)d_in[3];
    const float* b_out = (const float*)d_in[4];
    float* out = (float*)d_out;

    __nv_bfloat16 *qkvh, *qkvl;
    __nv_bfloat16 *win_hi, *win_lo, *wout_hi, *wout_lo;
    __nv_bfloat16 *xt_hi, *xt_lo, *at_hi, *at_lo;
    cudaGetSymbolAddress((void**)&qkvh, g_qkvh);
    cudaGetSymbolAddress((void**)&qkvl, g_qkvl);
    cudaGetSymbolAddress((void**)&win_hi, g_win_hi);
    cudaGetSymbolAddress((void**)&win_lo, g_win_lo);
    cudaGetSymbolAddress((void**)&wout_hi, g_wout_hi);
    cudaGetSymbolAddress((void**)&wout_lo, g_wout_lo);
    cudaGetSymbolAddress((void**)&xt_hi, g_xt_hi);
    cudaGetSymbolAddress((void**)&xt_lo, g_xt_lo);
    cudaGetSymbolAddress((void**)&at_hi, g_at_hi);
    cudaGetSymbolAddress((void**)&at_lo, g_at_lo);

    cudaFuncSetAttribute(flash_attn_mma,
                         cudaFuncAttributeMaxDynamicSharedMemorySize,
                         FA_SMEM_BYTES);
    cudaFuncSetAttribute(gemm_mma_kernel,
                         cudaFuncAttributeMaxDynamicSharedMemorySize,
                         GEMM_SMEM);

    // Split conversions (weights + transposed x)
    {
        int n1 = C3 * C_DIM;
        convert_split<<<(n1 + 255) / 256, 256>>>(w_in, win_hi, win_lo, n1);
        int n2 = C_DIM * C_DIM;
        convert_split<<<(n2 + 255) / 256, 256>>>(w_out, wout_hi, wout_lo, n2);
        convert_split_T<<<dim3(C_DIM / 32, SEQ / 32, BATCH), 256>>>(x, xt_hi, xt_lo);
    }

    // 1) QKV projection -> bf16 hi/lo, Q rows pre-scaled by 1/8
    gemm_mma_kernel<<<dim3(SEQ / 128, C3 / 128, BATCH), 256, GEMM_SMEM>>>(
        win_hi, win_lo, xt_hi, xt_lo, b_in,
        nullptr, qkvh, qkvl, C3, C_DIM);

    // 2) Flash attention -> at_hi/at_lo [s][chan]
    flash_attn_mma<<<dim3(SEQ / 64, NHEADS, BATCH), 128, FA_SMEM_BYTES>>>(
        qkvh, qkvl, at_hi, at_lo);

    // 3) Out-projection straight into d_out (fp32)
    gemm_mma_kernel<<<dim3(SEQ / 128, C_DIM / 128, BATCH), 256, GEMM_SMEM>>>(
        wout_hi, wout_lo, at_hi, at_lo, b_out,
        out, nullptr, nullptr, C_DIM, 0);
}

// round 15
// speedup vs baseline: 3.9003x; 1.2396x over previous
#include <cuda_runtime.h>
#include <cuda_bf16.h>
#include <cuda_fp16.h>
#include <cstdint>
#include <cstddef>

// ===========================================================================
// Self-attention block on tensor cores.
//   Projections: mma.sync fp16, A (weights) split hi/lo, B (activations)
//                single fp16 -> 2 MMA terms.  fp32 accumulate.
//   Attention:   mma.sync bf16 3-term split (unchanged from R14).
//   x:          (8, 768, 32, 32) == (B, K, S), S contiguous
//   in_proj_w:  (2304, 768), in_proj_b: (2304,)
//   out_proj_w: (768, 768),  out_proj_b: (768,)
//   out:        (8, 768, 32, 32)
// ===========================================================================

#define BATCH   8
#define C_DIM   768
#define C3      2304
#define SEQ     1024
#define NHEADS  12
#define DHEAD   64

// ---------------- scratch (static __device__ globals; no allocation) -------
__device__ __nv_bfloat16 g_qkvh[(size_t)BATCH * C3 * SEQ];   // (B,2304,S) hi
__device__ __nv_bfloat16 g_qkvl[(size_t)BATCH * C3 * SEQ];   // (B,2304,S) lo

__device__ __half g_win_h[(size_t)C3 * C_DIM];
__device__ __half g_win_l[(size_t)C3 * C_DIM];
__device__ __half g_wout_h[(size_t)C_DIM * C_DIM];
__device__ __half g_wout_l[(size_t)C_DIM * C_DIM];
__device__ __half g_xt[(size_t)BATCH * SEQ * C_DIM];   // x^T [s][k] fp16
__device__ __half g_at[(size_t)BATCH * SEQ * C_DIM];   // attn out [s][k] fp16

// ---------------------------------------------------------------------------
// PTX helpers
// ---------------------------------------------------------------------------
__device__ __forceinline__ void mma16816bf(float* c, const uint32_t* a,
                                           const uint32_t* b)
{
    asm volatile(
        "mma.sync.aligned.m16n8k16.row.col.f32.bf16.bf16.f32 "
        "{%0,%1,%2,%3}, {%4,%5,%6,%7}, {%8,%9}, {%0,%1,%2,%3};"
        : "+f"(c[0]), "+f"(c[1]), "+f"(c[2]), "+f"(c[3])
        : "r"(a[0]), "r"(a[1]), "r"(a[2]), "r"(a[3]), "r"(b[0]), "r"(b[1]));
}
__device__ __forceinline__ void mma16816h(float* c, const uint32_t* a,
                                          const uint32_t* b)
{
    asm volatile(
        "mma.sync.aligned.m16n8k16.row.col.f32.f16.f16.f32 "
        "{%0,%1,%2,%3}, {%4,%5,%6,%7}, {%8,%9}, {%0,%1,%2,%3};"
        : "+f"(c[0]), "+f"(c[1]), "+f"(c[2]), "+f"(c[3])
        : "r"(a[0]), "r"(a[1]), "r"(a[2]), "r"(a[3]), "r"(b[0]), "r"(b[1]));
}

__device__ __forceinline__ void ldmx4(uint32_t* r, uint32_t saddr)
{
    asm volatile("ldmatrix.sync.aligned.m8n8.x4.shared.b16 {%0,%1,%2,%3}, [%4];"
                 : "=r"(r[0]), "=r"(r[1]), "=r"(r[2]), "=r"(r[3])
                 : "r"(saddr));
}
__device__ __forceinline__ void ldmx4t(uint32_t* r, uint32_t saddr)
{
    asm volatile("ldmatrix.sync.aligned.m8n8.x4.trans.shared.b16 {%0,%1,%2,%3}, [%4];"
                 : "=r"(r[0]), "=r"(r[1]), "=r"(r[2]), "=r"(r[3])
                 : "r"(saddr));
}

#define CP16(dst, src) \
    asm volatile("cp.async.cg.shared.global [%0], [%1], 16;" \
                 :: "r"(dst), "l"(src) : "memory")
#define CP_COMMIT() asm volatile("cp.async.commit_group;" ::: "memory")
#define CP_WAIT(n)  asm volatile("cp.async.wait_group %0;" :: "n"(n) : "memory")

__device__ __forceinline__ void split_pack(float x0, float x1,
                                           uint32_t& hi, uint32_t& lo)
{
    __nv_bfloat16 h0 = __float2bfloat16(x0);
    __nv_bfloat16 h1 = __float2bfloat16(x1);
    __nv_bfloat16 l0 = __float2bfloat16(x0 - __bfloat162float(h0));
    __nv_bfloat16 l1 = __float2bfloat16(x1 - __bfloat162float(h1));
    hi = (uint32_t)*(uint16_t*)&h0 | ((uint32_t)*(uint16_t*)&h1 << 16);
    lo = (uint32_t)*(uint16_t*)&l0 | ((uint32_t)*(uint16_t*)&l1 << 16);
}
__device__ __forceinline__ uint32_t pack_half2(float x0, float x1)
{
    __half h0 = __float2half(x0);
    __half h1 = __float2half(x1);
    return (uint32_t)*(uint16_t*)&h0 | ((uint32_t)*(uint16_t*)&h1 << 16);
}

// ---------------------------------------------------------------------------
// Conversions
// ---------------------------------------------------------------------------
__global__ void convert_split_h(const float* __restrict__ in,
                                __half* __restrict__ hi,
                                __half* __restrict__ lo, int n)
{
    int i = blockIdx.x * blockDim.x + threadIdx.x;
    if (i >= n) return;
    float x = in[i];
    __half h = __float2half(x);
    hi[i] = h;
    lo[i] = __float2half(x - __half2float(h));
}

// (B, K=768, S=1024) fp32 -> (B, S=1024, K=768) fp16 single
__global__ __launch_bounds__(256)
void convert_T_h(const float* __restrict__ in, __half* __restrict__ outh)
{
    __shared__ float t[32][33];
    const int b  = blockIdx.z;
    const int k0 = blockIdx.x * 32;
    const int s0 = blockIdx.y * 32;
    const int tx = threadIdx.x & 31;
    const int ty = threadIdx.x >> 5;

    const float* ib = in + ((size_t)b * C_DIM + k0) * SEQ + s0;
    #pragma unroll
    for (int r = 0; r < 4; r++) {
        int kr = ty + r * 8;
        t[kr][tx] = ib[(size_t)kr * SEQ + tx];
    }
    __syncthreads();
    const size_t ob = ((size_t)b * SEQ + s0) * C_DIM + k0;
    #pragma unroll
    for (int r = 0; r < 4; r++) {
        int sr = ty + r * 8;
        outh[ob + (size_t)sr * C_DIM + tx] = __float2half(t[tx][sr]);
    }
}

// ---------------------------------------------------------------------------
// GEMM: (M x 1024) = W (M x 768) @ X[b] (768 x 1024) + bias
// A = W fp16 hi/lo; B = Xt fp16 single.  2 MMA terms: Ah*B + Al*B.
// BM=128, BN=128, BK=32. 8 warps (4m x 2n), warp tile 32x64.
// cp.async 2-stage pipeline; ldmatrix fragments; p+1 B prefetch.
// Epilogue: OutH!=null -> bf16 hi/lo split (rows<scale_cut scaled 1/8);
//           else fp32 to Out.
// ---------------------------------------------------------------------------
#define GBK   32
#define LDA   40                       // fp16 pitch (80 B): conflict-free
#define HBUF  (128 * LDA * 2)          // 10240 B per matrix buffer
#define STAGE_BYTES (3 * HBUF)         // 30720 B (Ah | Al | B)
#define GEMM_SMEM   (2 * STAGE_BYTES)  // 61440 B
#define GN_ITER (C_DIM / GBK)          // 24

__global__ __launch_bounds__(256, 2)
void gemm_mma_kernel(const __half* __restrict__ Wh,
                     const __half* __restrict__ Wl,
                     const __half* __restrict__ Bt,
                     const float* __restrict__ bias,
                     float* __restrict__ Out,
                     __nv_bfloat16* __restrict__ OutH,
                     __nv_bfloat16* __restrict__ OutL,
                     int M, int scale_cut)
{
    extern __shared__ char gsm[];
    const uint32_t sbase = (uint32_t)__cvta_generic_to_shared(gsm);

    const int tid  = threadIdx.x;
    const int lane = tid & 31;
    const int wid  = tid >> 5;
    const int wm   = wid & 3;
    const int wn   = wid >> 2;

    const int b  = blockIdx.z;
    const int m0 = blockIdx.y * 128;
    const int n0 = blockIdx.x * 128;

    const int g = lane >> 2;
    const int t = lane & 3;

    const __half* Ah = Wh + (size_t)m0 * C_DIM;
    const __half* Al = Wl + (size_t)m0 * C_DIM;
    const __half* Bb = Bt + ((size_t)b * SEQ + n0) * C_DIM;

    const int a_row = wm * 32 + ((lane >> 3) & 1) * 8 + (lane & 7);
    const int a_k   = (lane >> 4) * 8;
    const int b_row = wn * 64 + ((lane >> 4) << 3) + (lane & 7);
    const int b_k   = ((lane >> 3) & 1) * 8;

    float acc[2][8][4];
    #pragma unroll
    for (int mf = 0; mf < 2; mf++)
        #pragma unroll
        for (int nf = 0; nf < 8; nf++)
            #pragma unroll
            for (int r = 0; r < 4; r++) acc[mf][nf][r] = 0.f;

    auto load_stage = [&](int kt, int s) {
        const int k0 = kt * GBK;
        const uint32_t sb = sbase + s * STAGE_BYTES;
        #pragma unroll
        for (int r = 0; r < 2; r++) {
            int idx = tid + r * 256;
            int row = idx >> 2;
            int q   = idx & 3;
            uint32_t doff = (uint32_t)(row * (LDA * 2) + q * 16);
            CP16(sb + doff,
                 (const char*)(Ah + (size_t)row * C_DIM + k0) + q * 16);
            CP16(sb + HBUF + doff,
                 (const char*)(Al + (size_t)row * C_DIM + k0) + q * 16);
            CP16(sb + 2 * HBUF + doff,
                 (const char*)(Bb + (size_t)row * C_DIM + k0) + q * 16);
        }
    };

    load_stage(0, 0);
    CP_COMMIT();

    for (int kt = 0; kt < GN_ITER; kt++) {
        const int s = kt & 1;
        if (kt + 1 < GN_ITER) {
            load_stage(kt + 1, s ^ 1);
            CP_COMMIT();
            CP_WAIT(1);
        } else {
            CP_WAIT(0);
        }
        __syncthreads();

        const uint32_t sb = sbase + s * STAGE_BYTES;
        #pragma unroll
        for (int ks = 0; ks < 2; ks++) {
            const int kb = ks * 16;

            uint32_t ah[2][4], al[2][4];
            #pragma unroll
            for (int mf = 0; mf < 2; mf++) {
                uint32_t off = (uint32_t)(((a_row + mf * 16) * LDA + a_k + kb) * 2);
                ldmx4(ah[mf], sb + off);
                ldmx4(al[mf], sb + HBUF + off);
            }

            // B fragment prefetch pipeline across p
            uint32_t bcur[4], bnxt[4];
            ldmx4(bcur, sb + 2 * HBUF +
                  (uint32_t)((b_row * LDA + b_k + kb) * 2));

            #pragma unroll
            for (int p = 0; p < 4; p++) {
                if (p < 3) {
                    uint32_t boff = (uint32_t)(((b_row + (p + 1) * 16) * LDA
                                                + b_k + kb) * 2);
                    ldmx4(bnxt, sb + 2 * HBUF + boff);
                }
                #pragma unroll
                for (int mf = 0; mf < 2; mf++) {
                    mma16816h(acc[mf][2 * p],     ah[mf], bcur);
                    mma16816h(acc[mf][2 * p],     al[mf], bcur);
                    mma16816h(acc[mf][2 * p + 1], ah[mf], bcur + 2);
                    mma16816h(acc[mf][2 * p + 1], al[mf], bcur + 2);
                }
                #pragma unroll
                for (int r = 0; r < 4; r++) bcur[r] = bnxt[r];
            }
        }
        __syncthreads();
    }

    // ---- epilogue ----
    if (OutH) {
        __nv_bfloat16* OH = OutH + (size_t)b * M * SEQ;
        __nv_bfloat16* OL = OutL + (size_t)b * M * SEQ;
        #pragma unroll
        for (int mf = 0; mf < 2; mf++) {
            int m_lo = m0 + wm * 32 + mf * 16 + g;
            int m_hi = m_lo + 8;
            float rs0 = (m_lo < scale_cut) ? 0.125f : 1.0f;
            float rs1 = (m_hi < scale_cut) ? 0.125f : 1.0f;
            float bv0 = bias[m_lo];
            float bv1 = bias[m_hi];
            #pragma unroll
            for (int nf = 0; nf < 8; nf++) {
                int n = n0 + wn * 64 + nf * 8 + t * 2;
                uint32_t h0, l0, h1, l1;
                split_pack((acc[mf][nf][0] + bv0) * rs0,
                           (acc[mf][nf][1] + bv0) * rs0, h0, l0);
                split_pack((acc[mf][nf][2] + bv1) * rs1,
                           (acc[mf][nf][3] + bv1) * rs1, h1, l1);
                *(uint32_t*)&OH[(size_t)m_lo * SEQ + n] = h0;
                *(uint32_t*)&OL[(size_t)m_lo * SEQ + n] = l0;
                *(uint32_t*)&OH[(size_t)m_hi * SEQ + n] = h1;
                *(uint32_t*)&OL[(size_t)m_hi * SEQ + n] = l1;
            }
        }
    } else {
        float* Ob = Out + (size_t)b * M * SEQ;
        #pragma unroll
        for (int mf = 0; mf < 2; mf++) {
            int m_lo = m0 + wm * 32 + mf * 16 + g;
            int m_hi = m_lo + 8;
            float bv0 = bias[m_lo];
            float bv1 = bias[m_hi];
            #pragma unroll
            for (int nf = 0; nf < 8; nf++) {
                int n = n0 + wn * 64 + nf * 8 + t * 2;
                float2 v0 = make_float2(acc[mf][nf][0] + bv0, acc[mf][nf][1] + bv0);
                float2 v1 = make_float2(acc[mf][nf][2] + bv1, acc[mf][nf][3] + bv1);
                *(float2*)&Ob[(size_t)m_lo * SEQ + n] = v0;
                *(float2*)&Ob[(size_t)m_hi * SEQ + n] = v1;
            }
        }
    }
}

// ---------------------------------------------------------------------------
// Flash attention on tensor cores (bf16 3-term; structure unchanged from
// passing R14). Output now written as fp16 single [s][chan] for the
// out-projection's B operand.
// ---------------------------------------------------------------------------
#define FA_SMEM_BYTES (6 * 8192)

__global__ __launch_bounds__(128)
void flash_attn_mma(const __nv_bfloat16* __restrict__ qkvh,
                    const __nv_bfloat16* __restrict__ qkvl,
                    __half* __restrict__ at)
{
    extern __shared__ char smraw[];
    const uint32_t sb = (uint32_t)__cvta_generic_to_shared(smraw);
    const uint32_t SQH = sb, SQL = sb + 8192, SKH = sb + 16384,
                   SKL = sb + 24576, SVH = sb + 32768, SVL = sb + 40960;

    const int b  = blockIdx.z;
    const int h  = blockIdx.y;
    const int q0 = blockIdx.x * 64;

    const size_t hoff = ((size_t)b * C3 + h * DHEAD) * SEQ;
    const __nv_bfloat16* Qh = qkvh + hoff;
    const __nv_bfloat16* Ql = qkvl + hoff;
    const __nv_bfloat16* Kh = qkvh + hoff + (size_t)C_DIM * SEQ;
    const __nv_bfloat16* Kl = qkvl + hoff + (size_t)C_DIM * SEQ;
    const __nv_bfloat16* Vh = qkvh + hoff + (size_t)(2 * C_DIM) * SEQ;
    const __nv_bfloat16* Vl = qkvl + hoff + (size_t)(2 * C_DIM) * SEQ;

    const int tid  = threadIdx.x;
    const int lane = tid & 31;
    const int wid  = tid >> 5;
    const int g    = lane >> 2;
    const int t    = lane & 3;
    const int qw   = wid * 16;
    const int m4   = lane >> 3;
    const int j    = lane & 7;

    auto stage_tile = [&](const __nv_bfloat16* src, uint32_t dst, int s0) {
        #pragma unroll
        for (int r = 0; r < 4; r++) {
            int i   = tid + r * 128;
            int row = i >> 3;
            int q   = i & 7;
            uint32_t d = dst + (uint32_t)(row * 128 + ((q ^ (row & 7)) << 4));
            CP16(d, (const char*)(src + (size_t)row * SEQ + s0 + q * 8));
        }
    };

    stage_tile(Qh, SQH, q0);
    stage_tile(Ql, SQL, q0);
    stage_tile(Kh, SKH, 0);
    stage_tile(Kl, SKL, 0);
    stage_tile(Vh, SVH, 0);
    stage_tile(Vl, SVL, 0);
    CP_COMMIT();

    float o[8][4];
    float mrow[2], lrow[2];
    #pragma unroll
    for (int nt = 0; nt < 8; nt++)
        #pragma unroll
        for (int r = 0; r < 4; r++) o[nt][r] = 0.f;
    mrow[0] = mrow[1] = -1e30f;
    lrow[0] = lrow[1] = 0.f;

    for (int kt = 0; kt < SEQ / 64; kt++) {
        CP_WAIT(0);
        __syncthreads();

        float s[8][4];
        #pragma unroll
        for (int nt = 0; nt < 8; nt++)
            #pragma unroll
            for (int r = 0; r < 4; r++) s[nt][r] = 0.f;

        #pragma unroll
        for (int ks = 0; ks < 4; ks++) {
            const int kb = ks * 16;

            int ad = kb + (m4 >> 1) * 8 + j;
            int aq = qw + (m4 & 1) * 8;
            uint32_t aoff = (uint32_t)(ad * 128 + ((((aq >> 3) & 7) ^ (ad & 7)) << 4));
            uint32_t ah[4], al[4];
            ldmx4t(ah, SQH + aoff);
            ldmx4t(al, SQL + aoff);

            #pragma unroll
            for (int p = 0; p < 4; p++) {
                int bd = kb + (m4 & 1) * 8 + j;
                int bc = p * 16 + (m4 >> 1) * 8;
                uint32_t boff = (uint32_t)(bd * 128 + ((((bc >> 3) & 7) ^ (bd & 7)) << 4));
                uint32_t kh[4], kl[4];
                ldmx4t(kh, SKH + boff);
                ldmx4t(kl, SKL + boff);
                mma16816bf(s[2 * p],     ah, kh);
                mma16816bf(s[2 * p],     ah, kl);
                mma16816bf(s[2 * p],     al, kh);
                mma16816bf(s[2 * p + 1], ah, kh + 2);
                mma16816bf(s[2 * p + 1], ah, kl + 2);
                mma16816bf(s[2 * p + 1], al, kh + 2);
            }
        }

        #pragma unroll
        for (int ri = 0; ri < 2; ri++) {
            const int c0 = ri * 2, c1 = ri * 2 + 1;
            float mx = -1e30f;
            #pragma unroll
            for (int nt = 0; nt < 8; nt++)
                mx = fmaxf(mx, fmaxf(s[nt][c0], s[nt][c1]));
            mx = fmaxf(mx, __shfl_xor_sync(0xffffffffu, mx, 1));
            mx = fmaxf(mx, __shfl_xor_sync(0xffffffffu, mx, 2));

            float mnew = fmaxf(mrow[ri], mx);
            float corr = __expf(mrow[ri] - mnew);

            float rsum = 0.f;
            #pragma unroll
            for (int nt = 0; nt < 8; nt++) {
                float p0 = __expf(s[nt][c0] - mnew);
                float p1 = __expf(s[nt][c1] - mnew);
                s[nt][c0] = p0;
                s[nt][c1] = p1;
                rsum += p0 + p1;
            }
            rsum += __shfl_xor_sync(0xffffffffu, rsum, 1);
            rsum += __shfl_xor_sync(0xffffffffu, rsum, 2);

            lrow[ri] = lrow[ri] * corr + rsum;
            mrow[ri] = mnew;
            #pragma unroll
            for (int nt = 0; nt < 8; nt++) {
                o[nt][c0] *= corr;
                o[nt][c1] *= corr;
            }
        }

        #pragma unroll
        for (int ks = 0; ks < 4; ks++) {
            uint32_t ph[4], pl[4];
            split_pack(s[2 * ks][0],     s[2 * ks][1],     ph[0], pl[0]);
            split_pack(s[2 * ks][2],     s[2 * ks][3],     ph[1], pl[1]);
            split_pack(s[2 * ks + 1][0], s[2 * ks + 1][1], ph[2], pl[2]);
            split_pack(s[2 * ks + 1][2], s[2 * ks + 1][3], ph[3], pl[3]);

            const int kb = ks * 16;
            #pragma unroll
            for (int p = 0; p < 4; p++) {
                int vd = p * 16 + (m4 >> 1) * 8 + j;
                int vch = (kb >> 3) + (m4 & 1);
                uint32_t voff = (uint32_t)(vd * 128 + ((vch ^ (vd & 7)) << 4));
                uint32_t vh[4], vl[4];
                ldmx4(vh, SVH + voff);
                ldmx4(vl, SVL + voff);
                mma16816bf(o[2 * p],     ph, vh);
                mma16816bf(o[2 * p],     ph, vl);
                mma16816bf(o[2 * p],     pl, vh);
                mma16816bf(o[2 * p + 1], ph, vh + 2);
                mma16816bf(o[2 * p + 1], ph, vl + 2);
                mma16816bf(o[2 * p + 1], pl, vh + 2);
            }
        }
        __syncthreads();

        if (kt + 1 < SEQ / 64) {
            const int k0 = (kt + 1) * 64;
            stage_tile(Kh, SKH, k0);
            stage_tile(Kl, SKL, k0);
            stage_tile(Vh, SVH, k0);
            stage_tile(Vl, SVL, k0);
            CP_COMMIT();
        }
    }

    // ---- epilogue: normalize, write fp16 at[s][chan] ----
    const float inv0 = 1.0f / lrow[0];
    const float inv1 = 1.0f / lrow[1];
    const size_t rbase = ((size_t)b * SEQ + q0);
    const int cbase = h * DHEAD + t * 2;
    #pragma unroll
    for (int nt = 0; nt < 8; nt++) {
        int col = cbase + nt * 8;
        size_t i0 = (rbase + qw + g) * C_DIM + col;
        size_t i1 = (rbase + qw + 8 + g) * C_DIM + col;
        *(uint32_t*)&at[i0] = pack_half2(o[nt][0] * inv0, o[nt][1] * inv0);
        *(uint32_t*)&at[i1] = pack_half2(o[nt][2] * inv1, o[nt][3] * inv1);
    }
}

// ---------------------------------------------------------------------------
// Launch
// ---------------------------------------------------------------------------
extern "C" void kernel_launch(void* const* d_in, const int* in_sizes, int n_in,
                              void* d_out, int out_size)
{
    const float* x     = (const float*)d_in[0];
    const float* w_in  = (const float*)d_in[1];
    const float* b_in  = (const float*)d_in[2];
    const float* w_out = (const float*)d_in[3];
    const float* b_out = (const float*)d_in[4];
    float* out = (float*)d_out;

    __nv_bfloat16 *qkvh, *qkvl;
    __half *win_h, *win_l, *wout_h, *wout_l, *xt, *at;
    cudaGetSymbolAddress((void**)&qkvh, g_qkvh);
    cudaGetSymbolAddress((void**)&qkvl, g_qkvl);
    cudaGetSymbolAddress((void**)&win_h, g_win_h);
    cudaGetSymbolAddress((void**)&win_l, g_win_l);
    cudaGetSymbolAddress((void**)&wout_h, g_wout_h);
    cudaGetSymbolAddress((void**)&wout_l, g_wout_l);
    cudaGetSymbolAddress((void**)&xt, g_xt);
    cudaGetSymbolAddress((void**)&at, g_at);

    cudaFuncSetAttribute(flash_attn_mma,
                         cudaFuncAttributeMaxDynamicSharedMemorySize,
                         FA_SMEM_BYTES);
    cudaFuncSetAttribute(gemm_mma_kernel,
                         cudaFuncAttributeMaxDynamicSharedMemorySize,
                         GEMM_SMEM);

    // Conversions: weights -> fp16 hi/lo; x -> fp16 [s][k]
    {
        int n1 = C3 * C_DIM;
        convert_split_h<<<(n1 + 255) / 256, 256>>>(w_in, win_h, win_l, n1);
        int n2 = C_DIM * C_DIM;
        convert_split_h<<<(n2 + 255) / 256, 256>>>(w_out, wout_h, wout_l, n2);
        convert_T_h<<<dim3(C_DIM / 32, SEQ / 32, BATCH), 256>>>(x, xt);
    }

    // 1) QKV projection -> bf16 hi/lo, Q rows pre-scaled by 1/8
    gemm_mma_kernel<<<dim3(SEQ / 128, C3 / 128, BATCH), 256, GEMM_SMEM>>>(
        win_h, win_l, xt, b_in, nullptr, qkvh, qkvl, C3, C_DIM);

    // 2) Flash attention -> at fp16 [s][chan]
    flash_attn_mma<<<dim3(SEQ / 64, NHEADS, BATCH), 128, FA_SMEM_BYTES>>>(
        qkvh, qkvl, at);

    // 3) Out-projection straight into d_out (fp32)
    gemm_mma_kernel<<<dim3(SEQ / 128, C_DIM / 128, BATCH), 256, GEMM_SMEM>>>(
        wout_h, wout_l, at, b_out, out, nullptr, nullptr, C_DIM, 0);
}

// round 16
// speedup vs baseline: 4.7795x; 1.2254x over previous
#include <cuda_runtime.h>
#include <cuda_bf16.h>
#include <cuda_fp16.h>
#include <cstdint>
#include <cstddef>

// ===========================================================================
// Self-attention block on tensor cores (mma.sync fp16, fp32 accumulate).
//   Projections: A (weights) split fp16 hi/lo, B single fp16 -> 2 MMA terms.
//   Attention:   Q split fp16 hi/lo, K single fp16 -> 2 terms for S;
//                P single fp16, V single fp16     -> 1 term for O.
//   x:          (8, 768, 32, 32) == (B, K, S), S contiguous
//   in_proj_w:  (2304, 768), in_proj_b: (2304,)
//   out_proj_w: (768, 768),  out_proj_b: (768,)
//   out:        (8, 768, 32, 32)
// ===========================================================================

#define BATCH   8
#define C_DIM   768
#define C3      2304
#define SEQ     1024
#define NHEADS  12
#define DHEAD   64

// ---------------- scratch (static __device__ globals; no allocation) -------
__device__ __half g_qkvh[(size_t)BATCH * C3 * SEQ];  // (B,2304,S) fp16 hi
__device__ __half g_qkvl[(size_t)BATCH * C3 * SEQ];  // lo (valid for Q rows)

__device__ __half g_win_h[(size_t)C3 * C_DIM];
__device__ __half g_win_l[(size_t)C3 * C_DIM];
__device__ __half g_wout_h[(size_t)C_DIM * C_DIM];
__device__ __half g_wout_l[(size_t)C_DIM * C_DIM];
__device__ __half g_xt[(size_t)BATCH * SEQ * C_DIM];   // x^T [s][k] fp16
__device__ __half g_at[(size_t)BATCH * SEQ * C_DIM];   // attn out [s][k] fp16

// ---------------------------------------------------------------------------
// PTX helpers
// ---------------------------------------------------------------------------
__device__ __forceinline__ void mma16816h(float* c, const uint32_t* a,
                                          const uint32_t* b)
{
    asm volatile(
        "mma.sync.aligned.m16n8k16.row.col.f32.f16.f16.f32 "
        "{%0,%1,%2,%3}, {%4,%5,%6,%7}, {%8,%9}, {%0,%1,%2,%3};"
        : "+f"(c[0]), "+f"(c[1]), "+f"(c[2]), "+f"(c[3])
        : "r"(a[0]), "r"(a[1]), "r"(a[2]), "r"(a[3]), "r"(b[0]), "r"(b[1]));
}

__device__ __forceinline__ void ldmx4(uint32_t* r, uint32_t saddr)
{
    asm volatile("ldmatrix.sync.aligned.m8n8.x4.shared.b16 {%0,%1,%2,%3}, [%4];"
                 : "=r"(r[0]), "=r"(r[1]), "=r"(r[2]), "=r"(r[3])
                 : "r"(saddr));
}
__device__ __forceinline__ void ldmx4t(uint32_t* r, uint32_t saddr)
{
    asm volatile("ldmatrix.sync.aligned.m8n8.x4.trans.shared.b16 {%0,%1,%2,%3}, [%4];"
                 : "=r"(r[0]), "=r"(r[1]), "=r"(r[2]), "=r"(r[3])
                 : "r"(saddr));
}

#define CP16(dst, src) \
    asm volatile("cp.async.cg.shared.global [%0], [%1], 16;" \
                 :: "r"(dst), "l"(src) : "memory")
#define CP_COMMIT() asm volatile("cp.async.commit_group;" ::: "memory")
#define CP_WAIT(n)  asm volatile("cp.async.wait_group %0;" :: "n"(n) : "memory")

__device__ __forceinline__ void split_pack_h(float x0, float x1,
                                             uint32_t& hi, uint32_t& lo)
{
    __half h0 = __float2half(x0);
    __half h1 = __float2half(x1);
    __half l0 = __float2half(x0 - __half2float(h0));
    __half l1 = __float2half(x1 - __half2float(h1));
    hi = (uint32_t)*(uint16_t*)&h0 | ((uint32_t)*(uint16_t*)&h1 << 16);
    lo = (uint32_t)*(uint16_t*)&l0 | ((uint32_t)*(uint16_t*)&l1 << 16);
}
__device__ __forceinline__ uint32_t pack_half2(float x0, float x1)
{
    __half h0 = __float2half(x0);
    __half h1 = __float2half(x1);
    return (uint32_t)*(uint16_t*)&h0 | ((uint32_t)*(uint16_t*)&h1 << 16);
}

// ---------------------------------------------------------------------------
// Conversions
// ---------------------------------------------------------------------------
__global__ void convert_split_h(const float* __restrict__ in,
                                __half* __restrict__ hi,
                                __half* __restrict__ lo, int n)
{
    int i = blockIdx.x * blockDim.x + threadIdx.x;
    if (i >= n) return;
    float x = in[i];
    __half h = __float2half(x);
    hi[i] = h;
    lo[i] = __float2half(x - __half2float(h));
}

// (B, K=768, S=1024) fp32 -> (B, S=1024, K=768) fp16 single
__global__ __launch_bounds__(256)
void convert_T_h(const float* __restrict__ in, __half* __restrict__ outh)
{
    __shared__ float t[32][33];
    const int b  = blockIdx.z;
    const int k0 = blockIdx.x * 32;
    const int s0 = blockIdx.y * 32;
    const int tx = threadIdx.x & 31;
    const int ty = threadIdx.x >> 5;

    const float* ib = in + ((size_t)b * C_DIM + k0) * SEQ + s0;
    #pragma unroll
    for (int r = 0; r < 4; r++) {
        int kr = ty + r * 8;
        t[kr][tx] = ib[(size_t)kr * SEQ + tx];
    }
    __syncthreads();
    const size_t ob = ((size_t)b * SEQ + s0) * C_DIM + k0;
    #pragma unroll
    for (int r = 0; r < 4; r++) {
        int sr = ty + r * 8;
        outh[ob + (size_t)sr * C_DIM + tx] = __float2half(t[tx][sr]);
    }
}

// ---------------------------------------------------------------------------
// GEMM: (M x 1024) = W (M x 768) @ X[b] (768 x 1024) + bias
// A = W fp16 hi/lo; B = Xt fp16 single.  2 MMA terms.
// BM=128, BN=128, BK=32; cp.async 2-stage; ldmatrix; p+1 B prefetch.
// Epilogue: OutH!=null -> fp16 hi always; fp16 lo + 1/8 scaling only for
//           rows < scale_cut (Q rows).  Else fp32 to Out.
// ---------------------------------------------------------------------------
#define GBK   32
#define LDA   40
#define HBUF  (128 * LDA * 2)
#define STAGE_BYTES (3 * HBUF)
#define GEMM_SMEM   (2 * STAGE_BYTES)
#define GN_ITER (C_DIM / GBK)

__global__ __launch_bounds__(256, 2)
void gemm_mma_kernel(const __half* __restrict__ Wh,
                     const __half* __restrict__ Wl,
                     const __half* __restrict__ Bt,
                     const float* __restrict__ bias,
                     float* __restrict__ Out,
                     __half* __restrict__ OutH,
                     __half* __restrict__ OutL,
                     int M, int scale_cut)
{
    extern __shared__ char gsm[];
    const uint32_t sbase = (uint32_t)__cvta_generic_to_shared(gsm);

    const int tid  = threadIdx.x;
    const int lane = tid & 31;
    const int wid  = tid >> 5;
    const int wm   = wid & 3;
    const int wn   = wid >> 2;

    const int b  = blockIdx.z;
    const int m0 = blockIdx.y * 128;
    const int n0 = blockIdx.x * 128;

    const int g = lane >> 2;
    const int t = lane & 3;

    const __half* Ah = Wh + (size_t)m0 * C_DIM;
    const __half* Al = Wl + (size_t)m0 * C_DIM;
    const __half* Bb = Bt + ((size_t)b * SEQ + n0) * C_DIM;

    const int a_row = wm * 32 + ((lane >> 3) & 1) * 8 + (lane & 7);
    const int a_k   = (lane >> 4) * 8;
    const int b_row = wn * 64 + ((lane >> 4) << 3) + (lane & 7);
    const int b_k   = ((lane >> 3) & 1) * 8;

    float acc[2][8][4];
    #pragma unroll
    for (int mf = 0; mf < 2; mf++)
        #pragma unroll
        for (int nf = 0; nf < 8; nf++)
            #pragma unroll
            for (int r = 0; r < 4; r++) acc[mf][nf][r] = 0.f;

    auto load_stage = [&](int kt, int s) {
        const int k0 = kt * GBK;
        const uint32_t sb = sbase + s * STAGE_BYTES;
        #pragma unroll
        for (int r = 0; r < 2; r++) {
            int idx = tid + r * 256;
            int row = idx >> 2;
            int q   = idx & 3;
            uint32_t doff = (uint32_t)(row * (LDA * 2) + q * 16);
            CP16(sb + doff,
                 (const char*)(Ah + (size_t)row * C_DIM + k0) + q * 16);
            CP16(sb + HBUF + doff,
                 (const char*)(Al + (size_t)row * C_DIM + k0) + q * 16);
            CP16(sb + 2 * HBUF + doff,
                 (const char*)(Bb + (size_t)row * C_DIM + k0) + q * 16);
        }
    };

    load_stage(0, 0);
    CP_COMMIT();

    for (int kt = 0; kt < GN_ITER; kt++) {
        const int s = kt & 1;
        if (kt + 1 < GN_ITER) {
            load_stage(kt + 1, s ^ 1);
            CP_COMMIT();
            CP_WAIT(1);
        } else {
            CP_WAIT(0);
        }
        __syncthreads();

        const uint32_t sb = sbase + s * STAGE_BYTES;
        #pragma unroll
        for (int ks = 0; ks < 2; ks++) {
            const int kb = ks * 16;

            uint32_t ah[2][4], al[2][4];
            #pragma unroll
            for (int mf = 0; mf < 2; mf++) {
                uint32_t off = (uint32_t)(((a_row + mf * 16) * LDA + a_k + kb) * 2);
                ldmx4(ah[mf], sb + off);
                ldmx4(al[mf], sb + HBUF + off);
            }

            uint32_t bcur[4], bnxt[4];
            ldmx4(bcur, sb + 2 * HBUF +
                  (uint32_t)((b_row * LDA + b_k + kb) * 2));

            #pragma unroll
            for (int p = 0; p < 4; p++) {
                if (p < 3) {
                    uint32_t boff = (uint32_t)(((b_row + (p + 1) * 16) * LDA
                                                + b_k + kb) * 2);
                    ldmx4(bnxt, sb + 2 * HBUF + boff);
                }
                #pragma unroll
                for (int mf = 0; mf < 2; mf++) {
                    mma16816h(acc[mf][2 * p],     ah[mf], bcur);
                    mma16816h(acc[mf][2 * p],     al[mf], bcur);
                    mma16816h(acc[mf][2 * p + 1], ah[mf], bcur + 2);
                    mma16816h(acc[mf][2 * p + 1], al[mf], bcur + 2);
                }
                #pragma unroll
                for (int r = 0; r < 4; r++) bcur[r] = bnxt[r];
            }
        }
        __syncthreads();
    }

    // ---- epilogue ----
    if (OutH) {
        __half* OH = OutH + (size_t)b * M * SEQ;
        __half* OL = OutL + (size_t)b * M * SEQ;
        #pragma unroll
        for (int mf = 0; mf < 2; mf++) {
            int m_lo = m0 + wm * 32 + mf * 16 + g;
            int m_hi = m_lo + 8;
            bool q0r = (m_lo < scale_cut);
            bool q1r = (m_hi < scale_cut);
            float rs0 = q0r ? 0.125f : 1.0f;
            float rs1 = q1r ? 0.125f : 1.0f;
            float bv0 = bias[m_lo];
            float bv1 = bias[m_hi];
            #pragma unroll
            for (int nf = 0; nf < 8; nf++) {
                int n = n0 + wn * 64 + nf * 8 + t * 2;
                uint32_t h0, l0, h1, l1;
                split_pack_h((acc[mf][nf][0] + bv0) * rs0,
                             (acc[mf][nf][1] + bv0) * rs0, h0, l0);
                split_pack_h((acc[mf][nf][2] + bv1) * rs1,
                             (acc[mf][nf][3] + bv1) * rs1, h1, l1);
                *(uint32_t*)&OH[(size_t)m_lo * SEQ + n] = h0;
                *(uint32_t*)&OH[(size_t)m_hi * SEQ + n] = h1;
                if (q0r) *(uint32_t*)&OL[(size_t)m_lo * SEQ + n] = l0;
                if (q1r) *(uint32_t*)&OL[(size_t)m_hi * SEQ + n] = l1;
            }
        }
    } else {
        float* Ob = Out + (size_t)b * M * SEQ;
        #pragma unroll
        for (int mf = 0; mf < 2; mf++) {
            int m_lo = m0 + wm * 32 + mf * 16 + g;
            int m_hi = m_lo + 8;
            float bv0 = bias[m_lo];
            float bv1 = bias[m_hi];
            #pragma unroll
            for (int nf = 0; nf < 8; nf++) {
                int n = n0 + wn * 64 + nf * 8 + t * 2;
                float2 v0 = make_float2(acc[mf][nf][0] + bv0, acc[mf][nf][1] + bv0);
                float2 v1 = make_float2(acc[mf][nf][2] + bv1, acc[mf][nf][3] + bv1);
                *(float2*)&Ob[(size_t)m_lo * SEQ + n] = v0;
                *(float2*)&Ob[(size_t)m_hi * SEQ + n] = v1;
            }
        }
    }
}

// ---------------------------------------------------------------------------
// Flash attention on tensor cores, per (batch, head, q-tile of 64).
// fp16 throughout: Q split hi/lo (pre-scaled 1/8), K single, V single.
//   S = Qh^T K + Ql^T K   (2 terms)
//   O += P V^T            (1 term, P packed fp16 from registers)
// Smem: 4 swizzled 64x64 fp16 buffers (Qh,Ql,K,V), 8 KB each = 32 KB.
// Output: fp16 [s][chan] for the out-projection.
// ---------------------------------------------------------------------------
#define FA_SMEM_BYTES (4 * 8192)

__global__ __launch_bounds__(128)
void flash_attn_mma(const __half* __restrict__ qkvh,
                    const __half* __restrict__ qkvl,
                    __half* __restrict__ at)
{
    extern __shared__ char smraw[];
    const uint32_t sb = (uint32_t)__cvta_generic_to_shared(smraw);
    const uint32_t SQH = sb, SQL = sb + 8192, SK = sb + 16384, SV = sb + 24576;

    const int b  = blockIdx.z;
    const int h  = blockIdx.y;
    const int q0 = blockIdx.x * 64;

    const size_t hoff = ((size_t)b * C3 + h * DHEAD) * SEQ;
    const __half* Qh = qkvh + hoff;
    const __half* Ql = qkvl + hoff;
    const __half* Kk = qkvh + hoff + (size_t)C_DIM * SEQ;
    const __half* Vv = qkvh + hoff + (size_t)(2 * C_DIM) * SEQ;

    const int tid  = threadIdx.x;
    const int lane = tid & 31;
    const int wid  = tid >> 5;
    const int g    = lane >> 2;
    const int t    = lane & 3;
    const int qw   = wid * 16;
    const int m4   = lane >> 3;
    const int j    = lane & 7;

    auto stage_tile = [&](const __half* src, uint32_t dst, int s0) {
        #pragma unroll
        for (int r = 0; r < 4; r++) {
            int i   = tid + r * 128;
            int row = i >> 3;
            int q   = i & 7;
            uint32_t d = dst + (uint32_t)(row * 128 + ((q ^ (row & 7)) << 4));
            CP16(d, (const char*)(src + (size_t)row * SEQ + s0 + q * 8));
        }
    };

    stage_tile(Qh, SQH, q0);
    stage_tile(Ql, SQL, q0);
    stage_tile(Kk, SK, 0);
    stage_tile(Vv, SV, 0);
    CP_COMMIT();

    float o[8][4];
    float mrow[2], lrow[2];
    #pragma unroll
    for (int nt = 0; nt < 8; nt++)
        #pragma unroll
        for (int r = 0; r < 4; r++) o[nt][r] = 0.f;
    mrow[0] = mrow[1] = -1e30f;
    lrow[0] = lrow[1] = 0.f;

    for (int kt = 0; kt < SEQ / 64; kt++) {
        CP_WAIT(0);
        __syncthreads();

        // ---- S = Q^T K (2 fp16 terms) ----
        float s[8][4];
        #pragma unroll
        for (int nt = 0; nt < 8; nt++)
            #pragma unroll
            for (int r = 0; r < 4; r++) s[nt][r] = 0.f;

        #pragma unroll
        for (int ks = 0; ks < 4; ks++) {
            const int kb = ks * 16;

            int ad = kb + (m4 >> 1) * 8 + j;
            int aq = qw + (m4 & 1) * 8;
            uint32_t aoff = (uint32_t)(ad * 128 + ((((aq >> 3) & 7) ^ (ad & 7)) << 4));
            uint32_t ah[4], al[4];
            ldmx4t(ah, SQH + aoff);
            ldmx4t(al, SQL + aoff);

            #pragma unroll
            for (int p = 0; p < 4; p++) {
                int bd = kb + (m4 & 1) * 8 + j;
                int bc = p * 16 + (m4 >> 1) * 8;
                uint32_t boff = (uint32_t)(bd * 128 + ((((bc >> 3) & 7) ^ (bd & 7)) << 4));
                uint32_t kf[4];
                ldmx4t(kf, SK + boff);
                mma16816h(s[2 * p],     ah, kf);
                mma16816h(s[2 * p],     al, kf);
                mma16816h(s[2 * p + 1], ah, kf + 2);
                mma16816h(s[2 * p + 1], al, kf + 2);
            }
        }

        // ---- online softmax (rows g, g+8; reduce across quad lanes) ----
        #pragma unroll
        for (int ri = 0; ri < 2; ri++) {
            const int c0 = ri * 2, c1 = ri * 2 + 1;
            float mx = -1e30f;
            #pragma unroll
            for (int nt = 0; nt < 8; nt++)
                mx = fmaxf(mx, fmaxf(s[nt][c0], s[nt][c1]));
            mx = fmaxf(mx, __shfl_xor_sync(0xffffffffu, mx, 1));
            mx = fmaxf(mx, __shfl_xor_sync(0xffffffffu, mx, 2));

            float mnew = fmaxf(mrow[ri], mx);
            float corr = __expf(mrow[ri] - mnew);

            float rsum = 0.f;
            #pragma unroll
            for (int nt = 0; nt < 8; nt++) {
                float p0 = __expf(s[nt][c0] - mnew);
                float p1 = __expf(s[nt][c1] - mnew);
                s[nt][c0] = p0;
                s[nt][c1] = p1;
                rsum += p0 + p1;
            }
            rsum += __shfl_xor_sync(0xffffffffu, rsum, 1);
            rsum += __shfl_xor_sync(0xffffffffu, rsum, 2);

            lrow[ri] = lrow[ri] * corr + rsum;
            mrow[ri] = mnew;
            #pragma unroll
            for (int nt = 0; nt < 8; nt++) {
                o[nt][c0] *= corr;
                o[nt][c1] *= corr;
            }
        }

        // ---- O += P V^T (1 fp16 term, P register-passed) ----
        #pragma unroll
        for (int ks = 0; ks < 4; ks++) {
            uint32_t ph[4];
            ph[0] = pack_half2(s[2 * ks][0],     s[2 * ks][1]);
            ph[1] = pack_half2(s[2 * ks][2],     s[2 * ks][3]);
            ph[2] = pack_half2(s[2 * ks + 1][0], s[2 * ks + 1][1]);
            ph[3] = pack_half2(s[2 * ks + 1][2], s[2 * ks + 1][3]);

            const int kb = ks * 16;
            #pragma unroll
            for (int p = 0; p < 4; p++) {
                int vd = p * 16 + (m4 >> 1) * 8 + j;
                int vch = (kb >> 3) + (m4 & 1);
                uint32_t voff = (uint32_t)(vd * 128 + ((vch ^ (vd & 7)) << 4));
                uint32_t vf[4];
                ldmx4(vf, SV + voff);
                mma16816h(o[2 * p],     ph, vf);
                mma16816h(o[2 * p + 1], ph, vf + 2);
            }
        }
        __syncthreads();

        if (kt + 1 < SEQ / 64) {
            const int k0 = (kt + 1) * 64;
            stage_tile(Kk, SK, k0);
            stage_tile(Vv, SV, k0);
            CP_COMMIT();
        }
    }

    // ---- epilogue: normalize, write fp16 at[s][chan] ----
    const float inv0 = 1.0f / lrow[0];
    const float inv1 = 1.0f / lrow[1];
    const size_t rbase = ((size_t)b * SEQ + q0);
    const int cbase = h * DHEAD + t * 2;
    #pragma unroll
    for (int nt = 0; nt < 8; nt++) {
        int col = cbase + nt * 8;
        size_t i0 = (rbase + qw + g) * C_DIM + col;
        size_t i1 = (rbase + qw + 8 + g) * C_DIM + col;
        *(uint32_t*)&at[i0] = pack_half2(o[nt][0] * inv0, o[nt][1] * inv0);
        *(uint32_t*)&at[i1] = pack_half2(o[nt][2] * inv1, o[nt][3] * inv1);
    }
}

// ---------------------------------------------------------------------------
// Launch
// ---------------------------------------------------------------------------
extern "C" void kernel_launch(void* const* d_in, const int* in_sizes, int n_in,
                              void* d_out, int out_size)
{
    const float* x     = (const float*)d_in[0];
    const float* w_in  = (const float*)d_in[1];
    const float* b_in  = (const float*)d_in[2];
    const float* w_out = (const float*)d_in[3];
    const float* b_out = (const float*)d_in[4];
    float* out = (float*)d_out;

    __half *qkvh, *qkvl;
    __half *win_h, *win_l, *wout_h, *wout_l, *xt, *at;
    cudaGetSymbolAddress((void**)&qkvh, g_qkvh);
    cudaGetSymbolAddress((void**)&qkvl, g_qkvl);
    cudaGetSymbolAddress((void**)&win_h, g_win_h);
    cudaGetSymbolAddress((void**)&win_l, g_win_l);
    cudaGetSymbolAddress((void**)&wout_h, g_wout_h);
    cudaGetSymbolAddress((void**)&wout_l, g_wout_l);
    cudaGetSymbolAddress((void**)&xt, g_xt);
    cudaGetSymbolAddress((void**)&at, g_at);

    cudaFuncSetAttribute(flash_attn_mma,
                         cudaFuncAttributeMaxDynamicSharedMemorySize,
                         FA_SMEM_BYTES);
    cudaFuncSetAttribute(gemm_mma_kernel,
                         cudaFuncAttributeMaxDynamicSharedMemorySize,
                         GEMM_SMEM);

    // Conversions: weights -> fp16 hi/lo; x -> fp16 [s][k]
    {
        int n1 = C3 * C_DIM;
        convert_split_h<<<(n1 + 255) / 256, 256>>>(w_in, win_h, win_l, n1);
        int n2 = C_DIM * C_DIM;
        convert_split_h<<<(n2 + 255) / 256, 256>>>(w_out, wout_h, wout_l, n2);
        convert_T_h<<<dim3(C_DIM / 32, SEQ / 32, BATCH), 256>>>(x, xt);
    }

    // 1) QKV projection -> fp16 hi (+lo for Q rows), Q pre-scaled by 1/8
    gemm_mma_kernel<<<dim3(SEQ / 128, C3 / 128, BATCH), 256, GEMM_SMEM>>>(
        win_h, win_l, xt, b_in, nullptr, qkvh, qkvl, C3, C_DIM);

    // 2) Flash attention -> at fp16 [s][chan]
    flash_attn_mma<<<dim3(SEQ / 64, NHEADS, BATCH), 128, FA_SMEM_BYTES>>>(
        qkvh, qkvl, at);

    // 3) Out-projection straight into d_out (fp32)
    gemm_mma_kernel<<<dim3(SEQ / 128, C_DIM / 128, BATCH), 256, GEMM_SMEM>>>(
        wout_h, wout_l, at, b_out, out, nullptr, nullptr, C_DIM, 0);
}

// round 17
// speedup vs baseline: 6.7683x; 1.4161x over previous
#include <cuda_runtime.h>
#include <cuda_bf16.h>
#include <cuda_fp16.h>
#include <cstdint>
#include <cstddef>

// ===========================================================================
// Self-attention block on tensor cores (mma.sync fp16, fp32 accumulate).
//   QKV proj:  W_in single fp16, x single fp16       -> 1 MMA term
//   Attention: Q,K,V,P all single fp16               -> 1 term per matmul
//   Out proj:  W_out split fp16 hi/lo, at single     -> 2 MMA terms (hedge)
// GEMMs: BM=128/BN=128/BK=32, 3-stage cp.async ring, 1 sync/iter, ldmatrix.
//   x:          (8, 768, 32, 32) == (B, K, S), S contiguous
//   in_proj_w:  (2304, 768), in_proj_b: (2304,)
//   out_proj_w: (768, 768),  out_proj_b: (768,)
//   out:        (8, 768, 32, 32)
// ===========================================================================

#define BATCH   8
#define C_DIM   768
#define C3      2304
#define SEQ     1024
#define NHEADS  12
#define DHEAD   64

// ---------------- scratch (static __device__ globals; no allocation) -------
__device__ __half g_qkv[(size_t)BATCH * C3 * SEQ];   // (B,2304,S) fp16, Q/8
__device__ __half g_win[(size_t)C3 * C_DIM];          // W_in fp16 single
__device__ __half g_wout_h[(size_t)C_DIM * C_DIM];    // W_out fp16 hi
__device__ __half g_wout_l[(size_t)C_DIM * C_DIM];    // W_out fp16 lo
__device__ __half g_xt[(size_t)BATCH * SEQ * C_DIM];  // x^T [s][k] fp16
__device__ __half g_at[(size_t)BATCH * SEQ * C_DIM];  // attn out [s][k] fp16

// ---------------------------------------------------------------------------
// PTX helpers
// ---------------------------------------------------------------------------
__device__ __forceinline__ void mma16816h(float* c, const uint32_t* a,
                                          const uint32_t* b)
{
    asm volatile(
        "mma.sync.aligned.m16n8k16.row.col.f32.f16.f16.f32 "
        "{%0,%1,%2,%3}, {%4,%5,%6,%7}, {%8,%9}, {%0,%1,%2,%3};"
        : "+f"(c[0]), "+f"(c[1]), "+f"(c[2]), "+f"(c[3])
        : "r"(a[0]), "r"(a[1]), "r"(a[2]), "r"(a[3]), "r"(b[0]), "r"(b[1]));
}

__device__ __forceinline__ void ldmx4(uint32_t* r, uint32_t saddr)
{
    asm volatile("ldmatrix.sync.aligned.m8n8.x4.shared.b16 {%0,%1,%2,%3}, [%4];"
                 : "=r"(r[0]), "=r"(r[1]), "=r"(r[2]), "=r"(r[3])
                 : "r"(saddr));
}
__device__ __forceinline__ void ldmx4t(uint32_t* r, uint32_t saddr)
{
    asm volatile("ldmatrix.sync.aligned.m8n8.x4.trans.shared.b16 {%0,%1,%2,%3}, [%4];"
                 : "=r"(r[0]), "=r"(r[1]), "=r"(r[2]), "=r"(r[3])
                 : "r"(saddr));
}

#define CP16(dst, src) \
    asm volatile("cp.async.cg.shared.global [%0], [%1], 16;" \
                 :: "r"(dst), "l"(src) : "memory")
#define CP_COMMIT() asm volatile("cp.async.commit_group;" ::: "memory")
#define CP_WAIT(n)  asm volatile("cp.async.wait_group %0;" :: "n"(n) : "memory")

__device__ __forceinline__ uint32_t pack_half2(float x0, float x1)
{
    __half h0 = __float2half(x0);
    __half h1 = __float2half(x1);
    return (uint32_t)*(uint16_t*)&h0 | ((uint32_t)*(uint16_t*)&h1 << 16);
}

// ---------------------------------------------------------------------------
// Conversions
// ---------------------------------------------------------------------------
__global__ void convert_h(const float* __restrict__ in,
                          __half* __restrict__ o, int n)
{
    int i = blockIdx.x * blockDim.x + threadIdx.x;
    if (i < n) o[i] = __float2half(in[i]);
}

__global__ void convert_split_h(const float* __restrict__ in,
                                __half* __restrict__ hi,
                                __half* __restrict__ lo, int n)
{
    int i = blockIdx.x * blockDim.x + threadIdx.x;
    if (i >= n) return;
    float x = in[i];
    __half h = __float2half(x);
    hi[i] = h;
    lo[i] = __float2half(x - __half2float(h));
}

// (B, K=768, S=1024) fp32 -> (B, S=1024, K=768) fp16 single
__global__ __launch_bounds__(256)
void convert_T_h(const float* __restrict__ in, __half* __restrict__ outh)
{
    __shared__ float t[32][33];
    const int b  = blockIdx.z;
    const int k0 = blockIdx.x * 32;
    const int s0 = blockIdx.y * 32;
    const int tx = threadIdx.x & 31;
    const int ty = threadIdx.x >> 5;

    const float* ib = in + ((size_t)b * C_DIM + k0) * SEQ + s0;
    #pragma unroll
    for (int r = 0; r < 4; r++) {
        int kr = ty + r * 8;
        t[kr][tx] = ib[(size_t)kr * SEQ + tx];
    }
    __syncthreads();
    const size_t ob = ((size_t)b * SEQ + s0) * C_DIM + k0;
    #pragma unroll
    for (int r = 0; r < 4; r++) {
        int sr = ty + r * 8;
        outh[ob + (size_t)sr * C_DIM + tx] = __float2half(t[tx][sr]);
    }
}

// ---------------------------------------------------------------------------
// GEMM: (M x 1024) = W (M x 768) @ X[b] (768 x 1024) + bias
// TERMS=1: A = Wh single.  TERMS=2: A = Wh + Wl split.
// B = Bt fp16 single, [n][k] row-major.
// BM=128, BN=128, BK=32; 3-stage cp.async ring, one __syncthreads per iter.
// Epilogue: OutH!=null -> fp16 (rows < scale_cut scaled by 1/8);
//           else fp32 to Out.
// ---------------------------------------------------------------------------
#define GBK   32
#define LDA   40
#define HBUF  (128 * LDA * 2)          // 10240 B per matrix buffer
#define GN_ITER (C_DIM / GBK)          // 24
#define GEMM_SMEM_MAX (3 * 3 * HBUF)   // 92160 B (TERMS=2 case)

template <int TERMS>
__global__ __launch_bounds__(256, 2)
void gemm_mma_kernel(const __half* __restrict__ Wh,
                     const __half* __restrict__ Wl,
                     const __half* __restrict__ Bt,
                     const float* __restrict__ bias,
                     float* __restrict__ Out,
                     __half* __restrict__ OutH,
                     int M, int scale_cut)
{
    constexpr int STAGE = (TERMS + 1) * HBUF;

    extern __shared__ char gsm[];
    const uint32_t sbase = (uint32_t)__cvta_generic_to_shared(gsm);

    const int tid  = threadIdx.x;
    const int lane = tid & 31;
    const int wid  = tid >> 5;
    const int wm   = wid & 3;
    const int wn   = wid >> 2;

    const int b  = blockIdx.z;
    const int m0 = blockIdx.y * 128;
    const int n0 = blockIdx.x * 128;

    const int g = lane >> 2;
    const int t = lane & 3;

    const __half* Ah = Wh + (size_t)m0 * C_DIM;
    const __half* Al = (TERMS == 2) ? (Wl + (size_t)m0 * C_DIM) : nullptr;
    const __half* Bb = Bt + ((size_t)b * SEQ + n0) * C_DIM;

    const int a_row = wm * 32 + ((lane >> 3) & 1) * 8 + (lane & 7);
    const int a_k   = (lane >> 4) * 8;
    const int b_row = wn * 64 + ((lane >> 4) << 3) + (lane & 7);
    const int b_k   = ((lane >> 3) & 1) * 8;

    float acc[2][8][4];
    #pragma unroll
    for (int mf = 0; mf < 2; mf++)
        #pragma unroll
        for (int nf = 0; nf < 8; nf++)
            #pragma unroll
            for (int r = 0; r < 4; r++) acc[mf][nf][r] = 0.f;

    auto load_stage = [&](int kt, int s) {
        const int k0 = kt * GBK;
        const uint32_t sb = sbase + s * STAGE;
        #pragma unroll
        for (int r = 0; r < 2; r++) {
            int idx = tid + r * 256;
            int row = idx >> 2;
            int q   = idx & 3;
            uint32_t doff = (uint32_t)(row * (LDA * 2) + q * 16);
            CP16(sb + doff,
                 (const char*)(Ah + (size_t)row * C_DIM + k0) + q * 16);
            if (TERMS == 2)
                CP16(sb + HBUF + doff,
                     (const char*)(Al + (size_t)row * C_DIM + k0) + q * 16);
            CP16(sb + TERMS * HBUF + doff,
                 (const char*)(Bb + (size_t)row * C_DIM + k0) + q * 16);
        }
    };

    load_stage(0, 0);
    CP_COMMIT();
    load_stage(1, 1);
    CP_COMMIT();

    int stage = 0;
    for (int kt = 0; kt < GN_ITER; kt++) {
        if (kt + 1 < GN_ITER) { CP_WAIT(1); } else { CP_WAIT(0); }
        __syncthreads();

        const uint32_t sb = sbase + stage * STAGE;
        #pragma unroll
        for (int ks = 0; ks < 2; ks++) {
            const int kb = ks * 16;

            uint32_t ah[2][4], al2[2][4];
            #pragma unroll
            for (int mf = 0; mf < 2; mf++) {
                uint32_t off = (uint32_t)(((a_row + mf * 16) * LDA + a_k + kb) * 2);
                ldmx4(ah[mf], sb + off);
                if (TERMS == 2) ldmx4(al2[mf], sb + HBUF + off);
            }

            uint32_t bcur[4], bnxt[4];
            ldmx4(bcur, sb + TERMS * HBUF +
                  (uint32_t)((b_row * LDA + b_k + kb) * 2));

            #pragma unroll
            for (int p = 0; p < 4; p++) {
                if (p < 3) {
                    uint32_t boff = (uint32_t)(((b_row + (p + 1) * 16) * LDA
                                                + b_k + kb) * 2);
                    ldmx4(bnxt, sb + TERMS * HBUF + boff);
                }
                #pragma unroll
                for (int mf = 0; mf < 2; mf++) {
                    mma16816h(acc[mf][2 * p],     ah[mf], bcur);
                    mma16816h(acc[mf][2 * p + 1], ah[mf], bcur + 2);
                    if (TERMS == 2) {
                        mma16816h(acc[mf][2 * p],     al2[mf], bcur);
                        mma16816h(acc[mf][2 * p + 1], al2[mf], bcur + 2);
                    }
                }
                #pragma unroll
                for (int r = 0; r < 4; r++) bcur[r] = bnxt[r];
            }
        }

        if (kt + 2 < GN_ITER) {
            load_stage(kt + 2, (stage + 2 >= 3) ? stage - 1 : stage + 2);
            CP_COMMIT();
        }
        stage = (stage + 1 == 3) ? 0 : stage + 1;
    }

    // ---- epilogue ----
    if (OutH) {
        __half* OH = OutH + (size_t)b * M * SEQ;
        #pragma unroll
        for (int mf = 0; mf < 2; mf++) {
            int m_lo = m0 + wm * 32 + mf * 16 + g;
            int m_hi = m_lo + 8;
            float rs0 = (m_lo < scale_cut) ? 0.125f : 1.0f;
            float rs1 = (m_hi < scale_cut) ? 0.125f : 1.0f;
            float bv0 = bias[m_lo];
            float bv1 = bias[m_hi];
            #pragma unroll
            for (int nf = 0; nf < 8; nf++) {
                int n = n0 + wn * 64 + nf * 8 + t * 2;
                *(uint32_t*)&OH[(size_t)m_lo * SEQ + n] =
                    pack_half2((acc[mf][nf][0] + bv0) * rs0,
                               (acc[mf][nf][1] + bv0) * rs0);
                *(uint32_t*)&OH[(size_t)m_hi * SEQ + n] =
                    pack_half2((acc[mf][nf][2] + bv1) * rs1,
                               (acc[mf][nf][3] + bv1) * rs1);
            }
        }
    } else {
        float* Ob = Out + (size_t)b * M * SEQ;
        #pragma unroll
        for (int mf = 0; mf < 2; mf++) {
            int m_lo = m0 + wm * 32 + mf * 16 + g;
            int m_hi = m_lo + 8;
            float bv0 = bias[m_lo];
            float bv1 = bias[m_hi];
            #pragma unroll
            for (int nf = 0; nf < 8; nf++) {
                int n = n0 + wn * 64 + nf * 8 + t * 2;
                float2 v0 = make_float2(acc[mf][nf][0] + bv0, acc[mf][nf][1] + bv0);
                float2 v1 = make_float2(acc[mf][nf][2] + bv1, acc[mf][nf][3] + bv1);
                *(float2*)&Ob[(size_t)m_lo * SEQ + n] = v0;
                *(float2*)&Ob[(size_t)m_hi * SEQ + n] = v1;
            }
        }
    }
}

// ---------------------------------------------------------------------------
// Flash attention, per (batch, head, q-tile of 64). All single fp16:
//   S = Q^T K (1 term, Q pre-scaled 1/8); O += P V^T (1 term).
// Smem: 3 swizzled 64x64 fp16 buffers (Q,K,V), 8 KB each = 24 KB.
// Output: fp16 [s][chan] for the out-projection.
// ---------------------------------------------------------------------------
#define FA_SMEM_BYTES (3 * 8192)

__global__ __launch_bounds__(128)
void flash_attn_mma(const __half* __restrict__ qkv,
                    __half* __restrict__ at)
{
    extern __shared__ char smraw[];
    const uint32_t sb = (uint32_t)__cvta_generic_to_shared(smraw);
    const uint32_t SQ = sb, SK = sb + 8192, SV = sb + 16384;

    const int b  = blockIdx.z;
    const int h  = blockIdx.y;
    const int q0 = blockIdx.x * 64;

    const size_t hoff = ((size_t)b * C3 + h * DHEAD) * SEQ;
    const __half* Qq = qkv + hoff;
    const __half* Kk = qkv + hoff + (size_t)C_DIM * SEQ;
    const __half* Vv = qkv + hoff + (size_t)(2 * C_DIM) * SEQ;

    const int tid  = threadIdx.x;
    const int lane = tid & 31;
    const int wid  = tid >> 5;
    const int g    = lane >> 2;
    const int t    = lane & 3;
    const int qw   = wid * 16;
    const int m4   = lane >> 3;
    const int j    = lane & 7;

    auto stage_tile = [&](const __half* src, uint32_t dst, int s0) {
        #pragma unroll
        for (int r = 0; r < 4; r++) {
            int i   = tid + r * 128;
            int row = i >> 3;
            int q   = i & 7;
            uint32_t d = dst + (uint32_t)(row * 128 + ((q ^ (row & 7)) << 4));
            CP16(d, (const char*)(src + (size_t)row * SEQ + s0 + q * 8));
        }
    };

    stage_tile(Qq, SQ, q0);
    stage_tile(Kk, SK, 0);
    stage_tile(Vv, SV, 0);
    CP_COMMIT();

    float o[8][4];
    float mrow[2], lrow[2];
    #pragma unroll
    for (int nt = 0; nt < 8; nt++)
        #pragma unroll
        for (int r = 0; r < 4; r++) o[nt][r] = 0.f;
    mrow[0] = mrow[1] = -1e30f;
    lrow[0] = lrow[1] = 0.f;

    for (int kt = 0; kt < SEQ / 64; kt++) {
        CP_WAIT(0);
        __syncthreads();

        // ---- S = Q^T K (1 fp16 term) ----
        float s[8][4];
        #pragma unroll
        for (int nt = 0; nt < 8; nt++)
            #pragma unroll
            for (int r = 0; r < 4; r++) s[nt][r] = 0.f;

        #pragma unroll
        for (int ks = 0; ks < 4; ks++) {
            const int kb = ks * 16;

            int ad = kb + (m4 >> 1) * 8 + j;
            int aq = qw + (m4 & 1) * 8;
            uint32_t aoff = (uint32_t)(ad * 128 + ((((aq >> 3) & 7) ^ (ad & 7)) << 4));
            uint32_t ah[4];
            ldmx4t(ah, SQ + aoff);

            #pragma unroll
            for (int p = 0; p < 4; p++) {
                int bd = kb + (m4 & 1) * 8 + j;
                int bc = p * 16 + (m4 >> 1) * 8;
                uint32_t boff = (uint32_t)(bd * 128 + ((((bc >> 3) & 7) ^ (bd & 7)) << 4));
                uint32_t kf[4];
                ldmx4t(kf, SK + boff);
                mma16816h(s[2 * p],     ah, kf);
                mma16816h(s[2 * p + 1], ah, kf + 2);
            }
        }

        // ---- online softmax (rows g, g+8; reduce across quad lanes) ----
        #pragma unroll
        for (int ri = 0; ri < 2; ri++) {
            const int c0 = ri * 2, c1 = ri * 2 + 1;
            float mx = -1e30f;
            #pragma unroll
            for (int nt = 0; nt < 8; nt++)
                mx = fmaxf(mx, fmaxf(s[nt][c0], s[nt][c1]));
            mx = fmaxf(mx, __shfl_xor_sync(0xffffffffu, mx, 1));
            mx = fmaxf(mx, __shfl_xor_sync(0xffffffffu, mx, 2));

            float mnew = fmaxf(mrow[ri], mx);
            float corr = __expf(mrow[ri] - mnew);

            float rsum = 0.f;
            #pragma unroll
            for (int nt = 0; nt < 8; nt++) {
                float p0 = __expf(s[nt][c0] - mnew);
                float p1 = __expf(s[nt][c1] - mnew);
                s[nt][c0] = p0;
                s[nt][c1] = p1;
                rsum += p0 + p1;
            }
            rsum += __shfl_xor_sync(0xffffffffu, rsum, 1);
            rsum += __shfl_xor_sync(0xffffffffu, rsum, 2);

            lrow[ri] = lrow[ri] * corr + rsum;
            mrow[ri] = mnew;
            #pragma unroll
            for (int nt = 0; nt < 8; nt++) {
                o[nt][c0] *= corr;
                o[nt][c1] *= corr;
            }
        }

        // ---- O += P V^T (1 fp16 term, P register-passed) ----
        #pragma unroll
        for (int ks = 0; ks < 4; ks++) {
            uint32_t ph[4];
            ph[0] = pack_half2(s[2 * ks][0],     s[2 * ks][1]);
            ph[1] = pack_half2(s[2 * ks][2],     s[2 * ks][3]);
            ph[2] = pack_half2(s[2 * ks + 1][0], s[2 * ks + 1][1]);
            ph[3] = pack_half2(s[2 * ks + 1][2], s[2 * ks + 1][3]);

            const int kb = ks * 16;
            #pragma unroll
            for (int p = 0; p < 4; p++) {
                int vd = p * 16 + (m4 >> 1) * 8 + j;
                int vch = (kb >> 3) + (m4 & 1);
                uint32_t voff = (uint32_t)(vd * 128 + ((vch ^ (vd & 7)) << 4));
                uint32_t vf[4];
                ldmx4(vf, SV + voff);
                mma16816h(o[2 * p],     ph, vf);
                mma16816h(o[2 * p + 1], ph, vf + 2);
            }
        }
        __syncthreads();

        if (kt + 1 < SEQ / 64) {
            const int k0 = (kt + 1) * 64;
            stage_tile(Kk, SK, k0);
            stage_tile(Vv, SV, k0);
            CP_COMMIT();
        }
    }

    // ---- epilogue: normalize, write fp16 at[s][chan] ----
    const float inv0 = 1.0f / lrow[0];
    const float inv1 = 1.0f / lrow[1];
    const size_t rbase = ((size_t)b * SEQ + q0);
    const int cbase = h * DHEAD + t * 2;
    #pragma unroll
    for (int nt = 0; nt < 8; nt++) {
        int col = cbase + nt * 8;
        size_t i0 = (rbase + qw + g) * C_DIM + col;
        size_t i1 = (rbase + qw + 8 + g) * C_DIM + col;
        *(uint32_t*)&at[i0] = pack_half2(o[nt][0] * inv0, o[nt][1] * inv0);
        *(uint32_t*)&at[i1] = pack_half2(o[nt][2] * inv1, o[nt][3] * inv1);
    }
}

// ---------------------------------------------------------------------------
// Launch
// ---------------------------------------------------------------------------
extern "C" void kernel_launch(void* const* d_in, const int* in_sizes, int n_in,
                              void* d_out, int out_size)
{
    const float* x     = (const float*)d_in[0];
    const float* w_in  = (const float*)d_in[1];
    const float* b_in  = (const float*)d_in[2];
    const float* w_out = (const float*)d_in[3];
    const float* b_out = (const float*)d_in[4];
    float* out = (float*)d_out;

    __half *qkv, *win, *wout_h, *wout_l, *xt, *at;
    cudaGetSymbolAddress((void**)&qkv, g_qkv);
    cudaGetSymbolAddress((void**)&win, g_win);
    cudaGetSymbolAddress((void**)&wout_h, g_wout_h);
    cudaGetSymbolAddress((void**)&wout_l, g_wout_l);
    cudaGetSymbolAddress((void**)&xt, g_xt);
    cudaGetSymbolAddress((void**)&at, g_at);

    cudaFuncSetAttribute(flash_attn_mma,
                         cudaFuncAttributeMaxDynamicSharedMemorySize,
                         FA_SMEM_BYTES);
    cudaFuncSetAttribute(gemm_mma_kernel<1>,
                         cudaFuncAttributeMaxDynamicSharedMemorySize,
                         3 * 2 * HBUF);
    cudaFuncSetAttribute(gemm_mma_kernel<2>,
                         cudaFuncAttributeMaxDynamicSharedMemorySize,
                         3 * 3 * HBUF);

    // Conversions: W_in -> fp16 single; W_out -> fp16 hi/lo; x -> fp16 [s][k]
    {
        int n1 = C3 * C_DIM;
        convert_h<<<(n1 + 255) / 256, 256>>>(w_in, win, n1);
        int n2 = C_DIM * C_DIM;
        convert_split_h<<<(n2 + 255) / 256, 256>>>(w_out, wout_h, wout_l, n2);
        convert_T_h<<<dim3(C_DIM / 32, SEQ / 32, BATCH), 256>>>(x, xt);
    }

    // 1) QKV projection (1-term) -> fp16, Q rows pre-scaled by 1/8
    gemm_mma_kernel<1><<<dim3(SEQ / 128, C3 / 128, BATCH), 256, 3 * 2 * HBUF>>>(
        win, nullptr, xt, b_in, nullptr, qkv, C3, C_DIM);

    // 2) Flash attention -> at fp16 [s][chan]
    flash_attn_mma<<<dim3(SEQ / 64, NHEADS, BATCH), 128, FA_SMEM_BYTES>>>(
        qkv, at);

    // 3) Out-projection (2-term) straight into d_out (fp32)
    gemm_mma_kernel<2><<<dim3(SEQ / 128, C_DIM / 128, BATCH), 256, 3 * 3 * HBUF>>>(
        wout_h, wout_l, at, b_out, out, nullptr, C_DIM, 0);
}